// round 1
// baseline (speedup 1.0000x reference)
#include <cuda_runtime.h>
#include <cuda_bf16.h>
#include <math.h>

#define NN 20000
#define NE 640000
#define ET (NE + NN)     // edges + self loops = 660000
#define FH 4             // heads
#define CC 64            // channels per head
#define HC 256           // heads*channels

// ---------------- device scratch (no allocation allowed) ----------------
__device__ float g_h[NN * HC];      // transformed features (layer 1 then layer 2)
__device__ float g_x2[NN * HC];     // elu(agg1 + b1)  -> input to layer 2
__device__ float g_agg2[NN * HC];   // layer-2 aggregation [N,H,C]
__device__ float g_as[NN * FH];
__device__ float g_ad[NN * FH];
__device__ int   g_deg[NN];
__device__ int   g_rowptr[NN + 1];
__device__ int   g_fill[NN];
__device__ int   g_csr_src[ET];

// ---------------- CSR build ----------------
__global__ void zero_deg_k() {
    int i = blockIdx.x * blockDim.x + threadIdx.x;
    if (i < NN) g_deg[i] = 0;
}

__global__ void hist_k(const int* __restrict__ ei) {
    int e = blockIdx.x * blockDim.x + threadIdx.x;
    if (e >= ET) return;
    int dst = (e < NE) ? ei[NE + e] : (e - NE);
    atomicAdd(&g_deg[dst], 1);
}

__global__ void scan_k() {
    __shared__ int sm[1024];
    int tid = threadIdx.x;
    const int CH = 20;                 // 1024*20 >= 20000
    int base = tid * CH;
    int sum = 0;
#pragma unroll
    for (int i = 0; i < CH; i++) {
        int idx = base + i;
        if (idx < NN) sum += g_deg[idx];
    }
    sm[tid] = sum;
    __syncthreads();
    for (int off = 1; off < 1024; off <<= 1) {
        int v = (tid >= off) ? sm[tid - off] : 0;
        __syncthreads();
        sm[tid] += v;
        __syncthreads();
    }
    int run = sm[tid] - sum;           // exclusive prefix
#pragma unroll
    for (int i = 0; i < CH; i++) {
        int idx = base + i;
        if (idx < NN) {
            g_rowptr[idx] = run;
            g_fill[idx] = run;
            run += g_deg[idx];
        }
    }
    if (tid == 0) g_rowptr[NN] = sm[1023];
}

__global__ void scatter_k(const int* __restrict__ ei) {
    int e = blockIdx.x * blockDim.x + threadIdx.x;
    if (e >= ET) return;
    int src, dst;
    if (e < NE) { src = ei[e]; dst = ei[NE + e]; }
    else        { src = dst = e - NE; }
    int p = atomicAdd(&g_fill[dst], 1);
    g_csr_src[p] = src;
}

// ---------------- GEMM: C[M,256] = A[M,K] @ B[K,256] ----------------
template <int K>
__global__ void gemm64_k(const float* __restrict__ A, const float* __restrict__ B,
                         float* __restrict__ C, int M) {
    const int BM = 64, BN = 64, BK = 16;
    __shared__ __align__(16) float As[BK][BM + 4];
    __shared__ __align__(16) float Bs[BK][BN];
    int t = threadIdx.x;
    int bm = blockIdx.y * BM, bn = blockIdx.x * BN;
    int tx = t % 16, ty = t / 16;
    float acc[4][4] = {};
    int ak = t % 16;          // k within A tile
    int am = t / 16;          // row base (step 16)
    int bnl = t % 64;         // col within B tile
    int bkl = t / 64;         // k base (step 4)

    for (int k0 = 0; k0 < K; k0 += BK) {
#pragma unroll
        for (int i = 0; i < 4; i++) {
            int m = bm + am + i * 16;
            As[ak][am + i * 16] = (m < M) ? A[m * K + k0 + ak] : 0.f;
        }
#pragma unroll
        for (int i = 0; i < 4; i++) {
            Bs[bkl + i * 4][bnl] = B[(k0 + bkl + i * 4) * 256 + bn + bnl];
        }
        __syncthreads();
#pragma unroll
        for (int kk = 0; kk < BK; kk++) {
            float4 a4 = *(const float4*)&As[kk][ty * 4];
            float4 b4 = *(const float4*)&Bs[kk][tx * 4];
            float a[4] = {a4.x, a4.y, a4.z, a4.w};
            float b[4] = {b4.x, b4.y, b4.z, b4.w};
#pragma unroll
            for (int i = 0; i < 4; i++)
#pragma unroll
                for (int j = 0; j < 4; j++)
                    acc[i][j] += a[i] * b[j];
        }
        __syncthreads();
    }
#pragma unroll
    for (int i = 0; i < 4; i++) {
        int m = bm + ty * 4 + i;
        if (m < M) {
#pragma unroll
            for (int j = 0; j < 4; j++)
                C[m * 256 + bn + tx * 4 + j] = acc[i][j];
        }
    }
}

// ---------------- per-(node,head) attention coefficients ----------------
__global__ void asad_k(const float* __restrict__ h, const float* __restrict__ atts,
                       const float* __restrict__ attd) {
    int warp = (blockIdx.x * blockDim.x + threadIdx.x) >> 5;
    int lane = threadIdx.x & 31;
    if (warp >= NN * FH) return;
    int n = warp >> 2, hd = warp & 3;
    float2 hv = *(const float2*)&h[n * HC + hd * CC + 2 * lane];
    float2 sv = *(const float2*)&atts[hd * CC + 2 * lane];
    float2 dv = *(const float2*)&attd[hd * CC + 2 * lane];
    float ps = hv.x * sv.x + hv.y * sv.y;
    float pd = hv.x * dv.x + hv.y * dv.y;
#pragma unroll
    for (int off = 16; off; off >>= 1) {
        ps += __shfl_xor_sync(0xffffffffu, ps, off);
        pd += __shfl_xor_sync(0xffffffffu, pd, off);
    }
    if (lane == 0) { g_as[warp] = ps; g_ad[warp] = pd; }
}

// ---------------- GAT aggregation: one warp per (dst,head) ----------------
__global__ void agg_k(const float* __restrict__ h, const float* __restrict__ bias,
                      float* __restrict__ out, int layer1) {
    int task = (blockIdx.x * blockDim.x + threadIdx.x) >> 5;
    int lane = threadIdx.x & 31;
    if (task >= NN * FH) return;
    int n = task >> 2, hd = task & 3;
    int beg = g_rowptr[n], end = g_rowptr[n + 1];
    float adv = g_ad[n * FH + hd];

    // pass 1: online softmax stats over incoming edges
    float m = -1e30f, s = 0.f;
    for (int i = beg + lane; i < end; i += 32) {
        int sc = g_csr_src[i];
        float e = g_as[sc * FH + hd] + adv;
        e = (e > 0.f) ? e : 0.2f * e;
        float mn = fmaxf(m, e);
        s = s * __expf(m - mn) + __expf(e - mn);
        m = mn;
    }
#pragma unroll
    for (int off = 16; off; off >>= 1) {
        float mo = __shfl_xor_sync(0xffffffffu, m, off);
        float so = __shfl_xor_sync(0xffffffffu, s, off);
        float mn = fmaxf(m, mo);
        s = s * __expf(m - mn) + so * __expf(mo - mn);
        m = mn;
    }
    float inv = 1.f / s;

    // pass 2: weighted gather of h[src]
    int c0 = 2 * lane;
    float a0 = 0.f, a1 = 0.f;
    for (int i = beg; i < end; i++) {
        int sc = g_csr_src[i];
        float e = g_as[sc * FH + hd] + adv;
        e = (e > 0.f) ? e : 0.2f * e;
        float al = __expf(e - m) * inv;
        float2 hv = *(const float2*)&h[sc * HC + hd * CC + c0];
        a0 += al * hv.x;
        a1 += al * hv.y;
    }
    int o = n * HC + hd * CC + c0;
    if (layer1) {
        float v0 = a0 + bias[hd * CC + c0];
        float v1 = a1 + bias[hd * CC + c0 + 1];
        v0 = (v0 > 0.f) ? v0 : (__expf(v0) - 1.f);   // elu
        v1 = (v1 > 0.f) ? v1 : (__expf(v1) - 1.f);
        out[o] = v0; out[o + 1] = v1;
    } else {
        out[o] = a0; out[o + 1] = a1;
    }
}

// ---------------- tail: head-mean + b2, then @Wout + bout ----------------
__global__ void final_k(const float* __restrict__ b2, const float* __restrict__ Wout,
                        const float* __restrict__ bout, float* __restrict__ out) {
    __shared__ float Ws[CC * 16];
    int t = threadIdx.x;
    for (int i = t; i < CC * 16; i += blockDim.x) Ws[i] = Wout[i];
    __syncthreads();
    int warp = (blockIdx.x * blockDim.x + t) >> 5;
    int lane = t & 31;
    if (warp >= NN) return;
    int n = warp;
    int c0 = 2 * lane;
    float v0 = 0.f, v1 = 0.f;
#pragma unroll
    for (int hd = 0; hd < FH; hd++) {
        float2 hv = *(const float2*)&g_agg2[n * HC + hd * CC + c0];
        v0 += hv.x; v1 += hv.y;
    }
    v0 = v0 * 0.25f + b2[c0];
    v1 = v1 * 0.25f + b2[c0 + 1];
    float p[16];
#pragma unroll
    for (int k = 0; k < 16; k++)
        p[k] = v0 * Ws[c0 * 16 + k] + v1 * Ws[(c0 + 1) * 16 + k];
#pragma unroll
    for (int k = 0; k < 16; k++) {
#pragma unroll
        for (int off = 16; off; off >>= 1)
            p[k] += __shfl_xor_sync(0xffffffffu, p[k], off);
    }
    if (lane < 16) out[n * 16 + lane] = p[lane] + bout[lane];
}

// ---------------- launch ----------------
extern "C" void kernel_launch(void* const* d_in, const int* in_sizes, int n_in,
                              void* d_out, int out_size) {
    const float* x     = (const float*)d_in[0];
    const int*   ei    = (const int*)d_in[1];
    const float* W1    = (const float*)d_in[2];
    const float* atts1 = (const float*)d_in[3];
    const float* attd1 = (const float*)d_in[4];
    const float* b1    = (const float*)d_in[5];
    const float* W2    = (const float*)d_in[6];
    const float* atts2 = (const float*)d_in[7];
    const float* attd2 = (const float*)d_in[8];
    const float* b2    = (const float*)d_in[9];
    const float* Wout  = (const float*)d_in[10];
    const float* bout  = (const float*)d_in[11];
    float* out = (float*)d_out;

    float* gh;   cudaGetSymbolAddress((void**)&gh, g_h);
    float* gx2;  cudaGetSymbolAddress((void**)&gx2, g_x2);
    float* gagg2; cudaGetSymbolAddress((void**)&gagg2, g_agg2);

    // CSR build (same graph for both layers)
    zero_deg_k<<<(NN + 255) / 256, 256>>>();
    hist_k<<<(ET + 255) / 256, 256>>>(ei);
    scan_k<<<1, 1024>>>();
    scatter_k<<<(ET + 255) / 256, 256>>>(ei);

    // ---- layer 1 ----
    gemm64_k<128><<<dim3(4, (NN + 63) / 64), 256>>>(x, W1, gh, NN);
    asad_k<<<(NN * FH * 32 + 255) / 256, 256>>>(gh, atts1, attd1);
    agg_k<<<(NN * FH * 32 + 255) / 256, 256>>>(gh, b1, gx2, 1);

    // ---- layer 2 ----
    gemm64_k<256><<<dim3(4, (NN + 63) / 64), 256>>>(gx2, W2, gh, NN);
    asad_k<<<(NN * FH * 32 + 255) / 256, 256>>>(gh, atts2, attd2);
    agg_k<<<(NN * FH * 32 + 255) / 256, 256>>>(gh, b2 /*unused*/, gagg2, 0);

    // ---- tail ----
    final_k<<<(NN * 32 + 255) / 256, 256>>>(b2, Wout, bout, out);
}

// round 2
// speedup vs baseline: 1.0007x; 1.0007x over previous
#include <cuda_runtime.h>
#include <cuda_bf16.h>
#include <math.h>

#define NN 20000
#define NNP 20096        // padded to multiple of 128 for GEMM tiles
#define NE 640000
#define ET (NE + NN)     // edges + self loops = 660000
#define FH 4             // heads
#define CC 64            // channels per head
#define HC 256           // heads*channels

// ---------------- device scratch (no allocation allowed) ----------------
__device__ float g_h[NN * HC];      // transformed features (layer 1 then layer 2)
__device__ float g_agg2[NN * HC];   // layer-2 aggregation [N,H,C]
__device__ float g_as[NN * FH];
__device__ float g_ad[NN * FH];
__device__ int   g_deg[NN];
__device__ int   g_rowptr[NN + 1];
__device__ int   g_fill[NN];
__device__ int   g_csr_src[ET];
// bf16 split operands: A' = [Ah, Al, Ah], B' = [Bh, Bh, Bl]  (K' = 3K)
__device__ __nv_bfloat16 g_a1[NNP * 384];
__device__ __nv_bfloat16 g_a2[NNP * 768];
__device__ __nv_bfloat16 g_b1[384 * 256];
__device__ __nv_bfloat16 g_b2[768 * 256];

// ---------------- CSR build ----------------
__global__ void zero_deg_k() {
    int i = blockIdx.x * blockDim.x + threadIdx.x;
    if (i < NN) g_deg[i] = 0;
}

__global__ void hist_k(const int* __restrict__ ei) {
    int e = blockIdx.x * blockDim.x + threadIdx.x;
    if (e >= ET) return;
    int dst = (e < NE) ? ei[NE + e] : (e - NE);
    atomicAdd(&g_deg[dst], 1);
}

__global__ void scan_k() {
    __shared__ int sm[1024];
    int tid = threadIdx.x;
    const int CH = 20;
    int base = tid * CH;
    int sum = 0;
#pragma unroll
    for (int i = 0; i < CH; i++) {
        int idx = base + i;
        if (idx < NN) sum += g_deg[idx];
    }
    sm[tid] = sum;
    __syncthreads();
    for (int off = 1; off < 1024; off <<= 1) {
        int v = (tid >= off) ? sm[tid - off] : 0;
        __syncthreads();
        sm[tid] += v;
        __syncthreads();
    }
    int run = sm[tid] - sum;
#pragma unroll
    for (int i = 0; i < CH; i++) {
        int idx = base + i;
        if (idx < NN) {
            g_rowptr[idx] = run;
            g_fill[idx] = run;
            run += g_deg[idx];
        }
    }
    if (tid == 0) g_rowptr[NN] = sm[1023];
}

__global__ void scatter_k(const int* __restrict__ ei) {
    int e = blockIdx.x * blockDim.x + threadIdx.x;
    if (e >= ET) return;
    int src, dst;
    if (e < NE) { src = ei[e]; dst = ei[NE + e]; }
    else        { src = dst = e - NE; }
    int p = atomicAdd(&g_fill[dst], 1);
    g_csr_src[p] = src;
}

// ---------------- bf16 split prep ----------------
__global__ void split_x_k(const float* __restrict__ x) {
    int i = blockIdx.x * blockDim.x + threadIdx.x;
    if (i >= NN * 128) return;
    int m = i >> 7, j = i & 127;
    float v = x[i];
    __nv_bfloat16 h = __float2bfloat16(v);
    __nv_bfloat16 l = __float2bfloat16(v - __bfloat162float(h));
    g_a1[m * 384 + j] = h;
    g_a1[m * 384 + 128 + j] = l;
    g_a1[m * 384 + 256 + j] = h;
}

template <int K>
__global__ void split_w_k(const float* __restrict__ W, __nv_bfloat16* __restrict__ Bp) {
    int i = blockIdx.x * blockDim.x + threadIdx.x;
    if (i >= K * 256) return;
    int r = i >> 8, c = i & 255;
    float v = W[i];
    __nv_bfloat16 h = __float2bfloat16(v);
    __nv_bfloat16 l = __float2bfloat16(v - __bfloat162float(h));
    Bp[r * 256 + c] = h;
    Bp[(K + r) * 256 + c] = h;
    Bp[(2 * K + r) * 256 + c] = l;
}

// ---------------- tensor-core GEMM: C[M,256] = A'[M,KP] @ B'[KP,256] ----------------
__device__ __forceinline__ void mma_bf16(float* c, const unsigned* a, const unsigned* b) {
    asm volatile(
        "mma.sync.aligned.m16n8k16.row.col.f32.bf16.bf16.f32 "
        "{%0,%1,%2,%3}, {%4,%5,%6,%7}, {%8,%9}, {%0,%1,%2,%3};\n"
        : "+f"(c[0]), "+f"(c[1]), "+f"(c[2]), "+f"(c[3])
        : "r"(a[0]), "r"(a[1]), "r"(a[2]), "r"(a[3]), "r"(b[0]), "r"(b[1]));
}

template <int KP>
__global__ void mma_gemm_k(const __nv_bfloat16* __restrict__ A,
                           const __nv_bfloat16* __restrict__ B,
                           float* __restrict__ C, int M) {
    const int BM = 128, BN = 64, BK = 32, LD = 40;  // LD = BK + 8 pad (80B rows, 16B-aligned)
    __shared__ __align__(16) __nv_bfloat16 As[BM * LD];
    __shared__ __align__(16) __nv_bfloat16 Bs[BN * LD];
    int t = threadIdx.x, lane = t & 31, wid = t >> 5;
    int wm = wid & 3, wn = wid >> 2;   // 4 warps along M, 2 along N
    int bm = blockIdx.y * BM, bn = blockIdx.x * BN;
    float acc[2][4][4] = {};
    int ar = t >> 1;                   // A copy: row 0..127
    int ac = (t & 1) * 16;             // elem offset 0 / 16
    int bnl = t & 63, bkl = t >> 6;    // B transpose load

    for (int k0 = 0; k0 < KP; k0 += BK) {
        __syncthreads();
        const __nv_bfloat16* ag = A + (size_t)(bm + ar) * KP + k0 + ac;
        unsigned sa = (unsigned)__cvta_generic_to_shared(&As[ar * LD + ac]);
        asm volatile("cp.async.ca.shared.global [%0], [%1], 16;\n" :: "r"(sa), "l"(ag) : "memory");
        asm volatile("cp.async.ca.shared.global [%0], [%1], 16;\n" :: "r"(sa + 16), "l"(ag + 8) : "memory");
#pragma unroll
        for (int i = 0; i < 8; i++) {
            int k = bkl + i * 4;
            Bs[bnl * LD + k] = B[(size_t)(k0 + k) * 256 + bn + bnl];
        }
        asm volatile("cp.async.commit_group;\n" ::: "memory");
        asm volatile("cp.async.wait_group 0;\n" ::: "memory");
        __syncthreads();
#pragma unroll
        for (int kk = 0; kk < BK; kk += 16) {
            unsigned af[2][4], bf[2][4];
#pragma unroll
            for (int mt = 0; mt < 2; mt++) {
                unsigned addr = (unsigned)__cvta_generic_to_shared(
                    &As[(wm * 32 + mt * 16 + (lane & 15)) * LD + kk + (lane >> 4) * 8]);
                asm volatile("ldmatrix.sync.aligned.m8n8.x4.shared.b16 {%0,%1,%2,%3}, [%4];\n"
                             : "=r"(af[mt][0]), "=r"(af[mt][1]), "=r"(af[mt][2]), "=r"(af[mt][3])
                             : "r"(addr));
            }
#pragma unroll
            for (int nb = 0; nb < 2; nb++) {
                int nr = wn * 32 + nb * 16 + (lane & 7) + ((lane >> 4) << 3);
                int kc = kk + ((lane >> 3) & 1) * 8;
                unsigned addr = (unsigned)__cvta_generic_to_shared(&Bs[nr * LD + kc]);
                asm volatile("ldmatrix.sync.aligned.m8n8.x4.shared.b16 {%0,%1,%2,%3}, [%4];\n"
                             : "=r"(bf[nb][0]), "=r"(bf[nb][1]), "=r"(bf[nb][2]), "=r"(bf[nb][3])
                             : "r"(addr));
            }
#pragma unroll
            for (int mt = 0; mt < 2; mt++)
#pragma unroll
                for (int nt = 0; nt < 4; nt++) {
                    unsigned bq[2] = { bf[nt >> 1][(nt & 1) * 2], bf[nt >> 1][(nt & 1) * 2 + 1] };
                    mma_bf16(acc[mt][nt], af[mt], bq);
                }
        }
    }
    int g = lane >> 2, tg = lane & 3;
#pragma unroll
    for (int mt = 0; mt < 2; mt++) {
        int r0 = bm + wm * 32 + mt * 16 + g;
#pragma unroll
        for (int nt = 0; nt < 4; nt++) {
            int c = bn + wn * 32 + nt * 8 + tg * 2;
            if (r0 < M)
                *(float2*)&C[(size_t)r0 * 256 + c] = make_float2(acc[mt][nt][0], acc[mt][nt][1]);
            if (r0 + 8 < M)
                *(float2*)&C[(size_t)(r0 + 8) * 256 + c] = make_float2(acc[mt][nt][2], acc[mt][nt][3]);
        }
    }
}

// ---------------- per-(node,head) attention coefficients ----------------
__global__ void asad_k(const float* __restrict__ h, const float* __restrict__ atts,
                       const float* __restrict__ attd) {
    int warp = (blockIdx.x * blockDim.x + threadIdx.x) >> 5;
    int lane = threadIdx.x & 31;
    if (warp >= NN * FH) return;
    int n = warp >> 2, hd = warp & 3;
    float2 hv = *(const float2*)&h[n * HC + hd * CC + 2 * lane];
    float2 sv = *(const float2*)&atts[hd * CC + 2 * lane];
    float2 dv = *(const float2*)&attd[hd * CC + 2 * lane];
    float ps = hv.x * sv.x + hv.y * sv.y;
    float pd = hv.x * dv.x + hv.y * dv.y;
#pragma unroll
    for (int off = 16; off; off >>= 1) {
        ps += __shfl_xor_sync(0xffffffffu, ps, off);
        pd += __shfl_xor_sync(0xffffffffu, pd, off);
    }
    if (lane == 0) { g_as[warp] = ps; g_ad[warp] = pd; }
}

// ---------------- GAT aggregation: one warp per (dst,head) ----------------
// layer1: out = elu(agg + b1) written directly as bf16 split into g_a2 (K'=768 layout)
// layer2: out written fp32 to g_agg2
__global__ void agg_k(const float* __restrict__ h, const float* __restrict__ bias,
                      float* __restrict__ outf, int layer1) {
    int task = (blockIdx.x * blockDim.x + threadIdx.x) >> 5;
    int lane = threadIdx.x & 31;
    if (task >= NN * FH) return;
    int n = task >> 2, hd = task & 3;
    int beg = g_rowptr[n], end = g_rowptr[n + 1];
    float adv = g_ad[n * FH + hd];

    // pass 1: online softmax stats
    float m = -1e30f, s = 0.f;
    for (int i = beg + lane; i < end; i += 32) {
        int sc = g_csr_src[i];
        float e = g_as[sc * FH + hd] + adv;
        e = (e > 0.f) ? e : 0.2f * e;
        float mn = fmaxf(m, e);
        s = s * __expf(m - mn) + __expf(e - mn);
        m = mn;
    }
#pragma unroll
    for (int off = 16; off; off >>= 1) {
        float mo = __shfl_xor_sync(0xffffffffu, m, off);
        float so = __shfl_xor_sync(0xffffffffu, s, off);
        float mn = fmaxf(m, mo);
        s = s * __expf(m - mn) + so * __expf(mo - mn);
        m = mn;
    }
    float inv = 1.f / s;

    // pass 2: weighted gather
    int c0 = 2 * lane;
    float a0 = 0.f, a1 = 0.f;
    for (int i = beg; i < end; i++) {
        int sc = g_csr_src[i];
        float e = g_as[sc * FH + hd] + adv;
        e = (e > 0.f) ? e : 0.2f * e;
        float al = __expf(e - m) * inv;
        float2 hv = *(const float2*)&h[sc * HC + hd * CC + c0];
        a0 += al * hv.x;
        a1 += al * hv.y;
    }
    int j = hd * CC + c0;
    if (layer1) {
        float v0 = a0 + bias[j];
        float v1 = a1 + bias[j + 1];
        v0 = (v0 > 0.f) ? v0 : (__expf(v0) - 1.f);   // elu
        v1 = (v1 > 0.f) ? v1 : (__expf(v1) - 1.f);
        __nv_bfloat16 h0 = __float2bfloat16(v0), h1 = __float2bfloat16(v1);
        __nv_bfloat16 l0 = __float2bfloat16(v0 - __bfloat162float(h0));
        __nv_bfloat16 l1 = __float2bfloat16(v1 - __bfloat162float(h1));
        __nv_bfloat162 hi2; hi2.x = h0; hi2.y = h1;
        __nv_bfloat162 lo2; lo2.x = l0; lo2.y = l1;
        *(__nv_bfloat162*)&g_a2[n * 768 + j]       = hi2;
        *(__nv_bfloat162*)&g_a2[n * 768 + 256 + j] = lo2;
        *(__nv_bfloat162*)&g_a2[n * 768 + 512 + j] = hi2;
    } else {
        outf[n * HC + j] = a0;
        outf[n * HC + j + 1] = a1;
    }
}

// ---------------- tail: head-mean + b2, then @Wout + bout ----------------
__global__ void final_k(const float* __restrict__ b2, const float* __restrict__ Wout,
                        const float* __restrict__ bout, float* __restrict__ out) {
    __shared__ float Ws[CC * 16];
    int t = threadIdx.x;
    for (int i = t; i < CC * 16; i += blockDim.x) Ws[i] = Wout[i];
    __syncthreads();
    int warp = (blockIdx.x * blockDim.x + t) >> 5;
    int lane = t & 31;
    if (warp >= NN) return;
    int n = warp;
    int c0 = 2 * lane;
    float v0 = 0.f, v1 = 0.f;
#pragma unroll
    for (int hd = 0; hd < FH; hd++) {
        float2 hv = *(const float2*)&g_agg2[n * HC + hd * CC + c0];
        v0 += hv.x; v1 += hv.y;
    }
    v0 = v0 * 0.25f + b2[c0];
    v1 = v1 * 0.25f + b2[c0 + 1];
    float p[16];
#pragma unroll
    for (int k = 0; k < 16; k++)
        p[k] = v0 * Ws[c0 * 16 + k] + v1 * Ws[(c0 + 1) * 16 + k];
#pragma unroll
    for (int k = 0; k < 16; k++) {
#pragma unroll
        for (int off = 16; off; off >>= 1)
            p[k] += __shfl_xor_sync(0xffffffffu, p[k], off);
    }
    if (lane < 16) out[n * 16 + lane] = p[lane] + bout[lane];
}

// ---------------- launch ----------------
extern "C" void kernel_launch(void* const* d_in, const int* in_sizes, int n_in,
                              void* d_out, int out_size) {
    const float* x     = (const float*)d_in[0];
    const int*   ei    = (const int*)d_in[1];
    const float* W1    = (const float*)d_in[2];
    const float* atts1 = (const float*)d_in[3];
    const float* attd1 = (const float*)d_in[4];
    const float* b1    = (const float*)d_in[5];
    const float* W2    = (const float*)d_in[6];
    const float* atts2 = (const float*)d_in[7];
    const float* attd2 = (const float*)d_in[8];
    const float* b2    = (const float*)d_in[9];
    const float* Wout  = (const float*)d_in[10];
    const float* bout  = (const float*)d_in[11];
    float* out = (float*)d_out;

    float* gh;    cudaGetSymbolAddress((void**)&gh, g_h);
    float* gagg2; cudaGetSymbolAddress((void**)&gagg2, g_agg2);
    __nv_bfloat16 *ga1, *ga2, *gb1, *gb2;
    cudaGetSymbolAddress((void**)&ga1, g_a1);
    cudaGetSymbolAddress((void**)&ga2, g_a2);
    cudaGetSymbolAddress((void**)&gb1, g_b1);
    cudaGetSymbolAddress((void**)&gb2, g_b2);

    // CSR build
    zero_deg_k<<<(NN + 255) / 256, 256>>>();
    hist_k<<<(ET + 255) / 256, 256>>>(ei);
    scan_k<<<1, 1024>>>();
    scatter_k<<<(ET + 255) / 256, 256>>>(ei);

    // bf16 split prep
    split_x_k<<<(NN * 128 + 255) / 256, 256>>>(x);
    split_w_k<128><<<(128 * 256 + 255) / 256, 256>>>(W1, gb1);
    split_w_k<256><<<(256 * 256 + 255) / 256, 256>>>(W2, gb2);

    // ---- layer 1 ----
    mma_gemm_k<384><<<dim3(4, (NNP / 128)), 256>>>(ga1, gb1, gh, NN);
    asad_k<<<(NN * FH * 32 + 255) / 256, 256>>>(gh, atts1, attd1);
    agg_k<<<(NN * FH * 32 + 255) / 256, 256>>>(gh, b1, nullptr, 1);  // -> g_a2 (bf16 split)

    // ---- layer 2 ----
    mma_gemm_k<768><<<dim3(4, (NNP / 128)), 256>>>(ga2, gb2, gh, NN);
    asad_k<<<(NN * FH * 32 + 255) / 256, 256>>>(gh, atts2, attd2);
    agg_k<<<(NN * FH * 32 + 255) / 256, 256>>>(gh, nullptr, gagg2, 0);

    // ---- tail ----
    final_k<<<(NN * 32 + 255) / 256, 256>>>(b2, Wout, bout, out);
}

// round 3
// speedup vs baseline: 1.0625x; 1.0618x over previous
#include <cuda_runtime.h>
#include <cuda_bf16.h>
#include <cuda_fp16.h>
#include <math.h>

#define NN 20000
#define NNP 20096        // padded to multiple of 128 for GEMM tiles
#define NE 640000
#define ET (NE + NN)     // edges + self loops = 660000
#define FH 4             // heads
#define CC 64            // channels per head
#define HC 256           // heads*channels

// ---------------- device scratch (no allocation allowed) ----------------
__device__ float g_h[NN * HC];      // transformed features fp32 (for attention logits)
__device__ __half g_hh[NN * HC];    // fp16 copy (for the per-edge gather)
__device__ float g_agg2[NN * HC];   // layer-2 aggregation [N,H,C]
__device__ float g_as[NN * FH];
__device__ float g_ad[NN * FH];
__device__ int   g_deg[NN];
__device__ int   g_rowptr[NN + 1];
__device__ int   g_fill[NN];
__device__ int   g_csr_src[ET];
// bf16 split operands. A' = [Ah, Al, Ah] (K'=3K). B' transposed: BT[n][k'] with
// k' = [Bh, Bh, Bl] so pairing gives AhBh + AlBh + AhBl.
__device__ __nv_bfloat16 g_a1[NNP * 384];
__device__ __nv_bfloat16 g_a2[NNP * 768];
__device__ __nv_bfloat16 g_bt1[256 * 384];
__device__ __nv_bfloat16 g_bt2[256 * 768];

// ---------------- CSR build ----------------
__global__ void zero_deg_k() {
    int i = blockIdx.x * blockDim.x + threadIdx.x;
    if (i < NN) g_deg[i] = 0;
}

__global__ void hist_k(const int* __restrict__ ei) {
    int e = blockIdx.x * blockDim.x + threadIdx.x;
    if (e >= ET) return;
    int dst = (e < NE) ? ei[NE + e] : (e - NE);
    atomicAdd(&g_deg[dst], 1);
}

__global__ void scan_k() {
    __shared__ int sm[1024];
    int tid = threadIdx.x;
    const int CH = 20;
    int base = tid * CH;
    int sum = 0;
#pragma unroll
    for (int i = 0; i < CH; i++) {
        int idx = base + i;
        if (idx < NN) sum += g_deg[idx];
    }
    sm[tid] = sum;
    __syncthreads();
    for (int off = 1; off < 1024; off <<= 1) {
        int v = (tid >= off) ? sm[tid - off] : 0;
        __syncthreads();
        sm[tid] += v;
        __syncthreads();
    }
    int run = sm[tid] - sum;
#pragma unroll
    for (int i = 0; i < CH; i++) {
        int idx = base + i;
        if (idx < NN) {
            g_rowptr[idx] = run;
            g_fill[idx] = run;
            run += g_deg[idx];
        }
    }
    if (tid == 0) g_rowptr[NN] = sm[1023];
}

__global__ void scatter_k(const int* __restrict__ ei) {
    int e = blockIdx.x * blockDim.x + threadIdx.x;
    if (e >= ET) return;
    int src, dst;
    if (e < NE) { src = ei[e]; dst = ei[NE + e]; }
    else        { src = dst = e - NE; }
    int p = atomicAdd(&g_fill[dst], 1);
    g_csr_src[p] = src;
}

// ---------------- bf16 split prep ----------------
__global__ void split_x_k(const float* __restrict__ x) {
    int i = blockIdx.x * blockDim.x + threadIdx.x;
    if (i >= NN * 128) return;
    int m = i >> 7, j = i & 127;
    float v = x[i];
    __nv_bfloat16 h = __float2bfloat16(v);
    __nv_bfloat16 l = __float2bfloat16(v - __bfloat162float(h));
    g_a1[m * 384 + j] = h;
    g_a1[m * 384 + 128 + j] = l;
    g_a1[m * 384 + 256 + j] = h;
}

// write W[K,256] transposed+split: BT[c][0..K)=hi, [K..2K)=hi, [2K..3K)=lo
template <int K>
__global__ void split_w_k(const float* __restrict__ W, __nv_bfloat16* __restrict__ BT) {
    int i = blockIdx.x * blockDim.x + threadIdx.x;
    if (i >= K * 256) return;
    int r = i >> 8, c = i & 255;
    float v = W[i];
    __nv_bfloat16 h = __float2bfloat16(v);
    __nv_bfloat16 l = __float2bfloat16(v - __bfloat162float(h));
    BT[c * (3 * K) + r] = h;
    BT[c * (3 * K) + K + r] = h;
    BT[c * (3 * K) + 2 * K + r] = l;
}

// ---------------- pipelined tensor-core GEMM ----------------
// C[M,256] = A'[M,KP] @ B'T[256,KP]^T ; also writes fp16 copy Ch.
__device__ __forceinline__ void mma_bf16(float* c, const unsigned* a, const unsigned* b) {
    asm volatile(
        "mma.sync.aligned.m16n8k16.row.col.f32.bf16.bf16.f32 "
        "{%0,%1,%2,%3}, {%4,%5,%6,%7}, {%8,%9}, {%0,%1,%2,%3};\n"
        : "+f"(c[0]), "+f"(c[1]), "+f"(c[2]), "+f"(c[3])
        : "r"(a[0]), "r"(a[1]), "r"(a[2]), "r"(a[3]), "r"(b[0]), "r"(b[1]));
}

template <int KP>
__global__ void mma_gemm_k(const __nv_bfloat16* __restrict__ A,
                           const __nv_bfloat16* __restrict__ BT,
                           float* __restrict__ C, __half* __restrict__ Ch, int M) {
    const int BM = 128, BN = 64, BK = 32, LD = 40;  // pad rows to 80B
    __shared__ __align__(16) __nv_bfloat16 As[2][BM * LD];
    __shared__ __align__(16) __nv_bfloat16 Bs[2][BN * LD];
    int t = threadIdx.x, lane = t & 31, wid = t >> 5;
    int wm = wid & 3, wn = wid >> 2;   // 4 warps along M, 2 along N
    int bm = blockIdx.y * BM, bn = blockIdx.x * BN;
    float acc[2][4][4] = {};

    int ar = t >> 1, ac = (t & 1) * 16;        // A: 2 x 16B per thread
    int brow = t >> 2, bcol = (t & 3) * 8;     // B: 1 x 16B per thread

    auto load_tile = [&](int k0, int st) {
        const __nv_bfloat16* ag = A + (size_t)(bm + ar) * KP + k0 + ac;
        unsigned sa = (unsigned)__cvta_generic_to_shared(&As[st][ar * LD + ac]);
        asm volatile("cp.async.ca.shared.global [%0], [%1], 16;\n" :: "r"(sa), "l"(ag) : "memory");
        asm volatile("cp.async.ca.shared.global [%0], [%1], 16;\n" :: "r"(sa + 16), "l"(ag + 8) : "memory");
        const __nv_bfloat16* bg = BT + (size_t)(bn + brow) * KP + k0 + bcol;
        unsigned sb = (unsigned)__cvta_generic_to_shared(&Bs[st][brow * LD + bcol]);
        asm volatile("cp.async.ca.shared.global [%0], [%1], 16;\n" :: "r"(sb), "l"(bg) : "memory");
        asm volatile("cp.async.commit_group;\n" ::: "memory");
    };

    load_tile(0, 0);
    const int NT = KP / BK;
    for (int i = 0; i < NT; i++) {
        if (i + 1 < NT) {
            load_tile((i + 1) * BK, (i + 1) & 1);
            asm volatile("cp.async.wait_group 1;\n" ::: "memory");
        } else {
            asm volatile("cp.async.wait_group 0;\n" ::: "memory");
        }
        __syncthreads();
        int st = i & 1;
#pragma unroll
        for (int kk = 0; kk < BK; kk += 16) {
            unsigned af[2][4], bf[2][4];
#pragma unroll
            for (int mt = 0; mt < 2; mt++) {
                unsigned addr = (unsigned)__cvta_generic_to_shared(
                    &As[st][(wm * 32 + mt * 16 + (lane & 15)) * LD + kk + (lane >> 4) * 8]);
                asm volatile("ldmatrix.sync.aligned.m8n8.x4.shared.b16 {%0,%1,%2,%3}, [%4];\n"
                             : "=r"(af[mt][0]), "=r"(af[mt][1]), "=r"(af[mt][2]), "=r"(af[mt][3])
                             : "r"(addr));
            }
#pragma unroll
            for (int nb = 0; nb < 2; nb++) {
                int nr = wn * 32 + nb * 16 + (lane & 7) + ((lane >> 4) << 3);
                int kc = kk + ((lane >> 3) & 1) * 8;
                unsigned addr = (unsigned)__cvta_generic_to_shared(&Bs[st][nr * LD + kc]);
                asm volatile("ldmatrix.sync.aligned.m8n8.x4.shared.b16 {%0,%1,%2,%3}, [%4];\n"
                             : "=r"(bf[nb][0]), "=r"(bf[nb][1]), "=r"(bf[nb][2]), "=r"(bf[nb][3])
                             : "r"(addr));
            }
#pragma unroll
            for (int mt = 0; mt < 2; mt++)
#pragma unroll
                for (int nt = 0; nt < 4; nt++) {
                    unsigned bq[2] = { bf[nt >> 1][(nt & 1) * 2], bf[nt >> 1][(nt & 1) * 2 + 1] };
                    mma_bf16(acc[mt][nt], af[mt], bq);
                }
        }
        __syncthreads();
    }

    int g = lane >> 2, tg = lane & 3;
#pragma unroll
    for (int mt = 0; mt < 2; mt++) {
        int r0 = bm + wm * 32 + mt * 16 + g;
#pragma unroll
        for (int nt = 0; nt < 4; nt++) {
            int c = bn + wn * 32 + nt * 8 + tg * 2;
            if (r0 < M) {
                *(float2*)&C[(size_t)r0 * 256 + c] = make_float2(acc[mt][nt][0], acc[mt][nt][1]);
                *(__half2*)&Ch[(size_t)r0 * 256 + c] = __floats2half2_rn(acc[mt][nt][0], acc[mt][nt][1]);
            }
            if (r0 + 8 < M) {
                *(float2*)&C[(size_t)(r0 + 8) * 256 + c] = make_float2(acc[mt][nt][2], acc[mt][nt][3]);
                *(__half2*)&Ch[(size_t)(r0 + 8) * 256 + c] = __floats2half2_rn(acc[mt][nt][2], acc[mt][nt][3]);
            }
        }
    }
}

// ---------------- per-(node,head) attention coefficients ----------------
__global__ void asad_k(const float* __restrict__ h, const float* __restrict__ atts,
                       const float* __restrict__ attd) {
    int warp = (blockIdx.x * blockDim.x + threadIdx.x) >> 5;
    int lane = threadIdx.x & 31;
    if (warp >= NN * FH) return;
    int n = warp >> 2, hd = warp & 3;
    float2 hv = *(const float2*)&h[n * HC + hd * CC + 2 * lane];
    float2 sv = *(const float2*)&atts[hd * CC + 2 * lane];
    float2 dv = *(const float2*)&attd[hd * CC + 2 * lane];
    float ps = hv.x * sv.x + hv.y * sv.y;
    float pd = hv.x * dv.x + hv.y * dv.y;
#pragma unroll
    for (int off = 16; off; off >>= 1) {
        ps += __shfl_xor_sync(0xffffffffu, ps, off);
        pd += __shfl_xor_sync(0xffffffffu, pd, off);
    }
    if (lane == 0) { g_as[warp] = ps; g_ad[warp] = pd; }
}

// ---------------- GAT aggregation: one warp per (dst,head) ----------------
__global__ void agg_k(const __half* __restrict__ hh, const float* __restrict__ bias,
                      float* __restrict__ outf, int layer1) {
    int task = (blockIdx.x * blockDim.x + threadIdx.x) >> 5;
    int lane = threadIdx.x & 31;
    if (task >= NN * FH) return;
    int n = task >> 2, hd = task & 3;
    int beg = g_rowptr[n], end = g_rowptr[n + 1];
    float adv = g_ad[n * FH + hd];

    // pass 1: online softmax stats
    float m = -1e30f, s = 0.f;
    for (int i = beg + lane; i < end; i += 32) {
        int sc = g_csr_src[i];
        float e = g_as[sc * FH + hd] + adv;
        e = (e > 0.f) ? e : 0.2f * e;
        float mn = fmaxf(m, e);
        s = s * __expf(m - mn) + __expf(e - mn);
        m = mn;
    }
#pragma unroll
    for (int off = 16; off; off >>= 1) {
        float mo = __shfl_xor_sync(0xffffffffu, m, off);
        float so = __shfl_xor_sync(0xffffffffu, s, off);
        float mn = fmaxf(m, mo);
        s = s * __expf(m - mn) + so * __expf(mo - mn);
        m = mn;
    }
    float inv = 1.f / s;

    // pass 2: weighted gather (fp16 features)
    int c0 = 2 * lane;
    float a0 = 0.f, a1 = 0.f;
    for (int i = beg; i < end; i++) {
        int sc = g_csr_src[i];
        float e = g_as[sc * FH + hd] + adv;
        e = (e > 0.f) ? e : 0.2f * e;
        float al = __expf(e - m) * inv;
        float2 hv = __half22float2(*(const __half2*)&hh[sc * HC + hd * CC + c0]);
        a0 += al * hv.x;
        a1 += al * hv.y;
    }
    int j = hd * CC + c0;
    if (layer1) {
        float v0 = a0 + bias[j];
        float v1 = a1 + bias[j + 1];
        v0 = (v0 > 0.f) ? v0 : (__expf(v0) - 1.f);   // elu
        v1 = (v1 > 0.f) ? v1 : (__expf(v1) - 1.f);
        __nv_bfloat16 h0 = __float2bfloat16(v0), h1 = __float2bfloat16(v1);
        __nv_bfloat16 l0 = __float2bfloat16(v0 - __bfloat162float(h0));
        __nv_bfloat16 l1 = __float2bfloat16(v1 - __bfloat162float(h1));
        __nv_bfloat162 hi2; hi2.x = h0; hi2.y = h1;
        __nv_bfloat162 lo2; lo2.x = l0; lo2.y = l1;
        *(__nv_bfloat162*)&g_a2[n * 768 + j]       = hi2;
        *(__nv_bfloat162*)&g_a2[n * 768 + 256 + j] = lo2;
        *(__nv_bfloat162*)&g_a2[n * 768 + 512 + j] = hi2;
    } else {
        outf[n * HC + j] = a0;
        outf[n * HC + j + 1] = a1;
    }
}

// ---------------- tail: head-mean + b2, then @Wout + bout ----------------
__global__ void final_k(const float* __restrict__ b2, const float* __restrict__ Wout,
                        const float* __restrict__ bout, float* __restrict__ out) {
    __shared__ float Ws[CC * 16];
    int t = threadIdx.x;
    for (int i = t; i < CC * 16; i += blockDim.x) Ws[i] = Wout[i];
    __syncthreads();
    int warp = (blockIdx.x * blockDim.x + t) >> 5;
    int lane = t & 31;
    if (warp >= NN) return;
    int n = warp;
    int c0 = 2 * lane;
    float v0 = 0.f, v1 = 0.f;
#pragma unroll
    for (int hd = 0; hd < FH; hd++) {
        float2 hv = *(const float2*)&g_agg2[n * HC + hd * CC + c0];
        v0 += hv.x; v1 += hv.y;
    }
    v0 = v0 * 0.25f + b2[c0];
    v1 = v1 * 0.25f + b2[c0 + 1];
    float p[16];
#pragma unroll
    for (int k = 0; k < 16; k++)
        p[k] = v0 * Ws[c0 * 16 + k] + v1 * Ws[(c0 + 1) * 16 + k];
#pragma unroll
    for (int k = 0; k < 16; k++) {
#pragma unroll
        for (int off = 16; off; off >>= 1)
            p[k] += __shfl_xor_sync(0xffffffffu, p[k], off);
    }
    if (lane < 16) out[n * 16 + lane] = p[lane] + bout[lane];
}

// ---------------- launch ----------------
extern "C" void kernel_launch(void* const* d_in, const int* in_sizes, int n_in,
                              void* d_out, int out_size) {
    const float* x     = (const float*)d_in[0];
    const int*   ei    = (const int*)d_in[1];
    const float* W1    = (const float*)d_in[2];
    const float* atts1 = (const float*)d_in[3];
    const float* attd1 = (const float*)d_in[4];
    const float* b1    = (const float*)d_in[5];
    const float* W2    = (const float*)d_in[6];
    const float* atts2 = (const float*)d_in[7];
    const float* attd2 = (const float*)d_in[8];
    const float* b2    = (const float*)d_in[9];
    const float* Wout  = (const float*)d_in[10];
    const float* bout  = (const float*)d_in[11];
    float* out = (float*)d_out;

    float* gh;    cudaGetSymbolAddress((void**)&gh, g_h);
    __half* ghh;  cudaGetSymbolAddress((void**)&ghh, g_hh);
    float* gagg2; cudaGetSymbolAddress((void**)&gagg2, g_agg2);
    __nv_bfloat16 *ga1, *ga2, *gbt1, *gbt2;
    cudaGetSymbolAddress((void**)&ga1, g_a1);
    cudaGetSymbolAddress((void**)&ga2, g_a2);
    cudaGetSymbolAddress((void**)&gbt1, g_bt1);
    cudaGetSymbolAddress((void**)&gbt2, g_bt2);

    // CSR build
    zero_deg_k<<<(NN + 255) / 256, 256>>>();
    hist_k<<<(ET + 255) / 256, 256>>>(ei);
    scan_k<<<1, 1024>>>();
    scatter_k<<<(ET + 255) / 256, 256>>>(ei);

    // bf16 split prep
    split_x_k<<<(NN * 128 + 255) / 256, 256>>>(x);
    split_w_k<128><<<(128 * 256 + 255) / 256, 256>>>(W1, gbt1);
    split_w_k<256><<<(256 * 256 + 255) / 256, 256>>>(W2, gbt2);

    // ---- layer 1 ----
    mma_gemm_k<384><<<dim3(4, NNP / 128), 256>>>(ga1, gbt1, gh, ghh, NN);
    asad_k<<<(NN * FH * 32 + 255) / 256, 256>>>(gh, atts1, attd1);
    agg_k<<<(NN * FH * 32 + 255) / 256, 256>>>(ghh, b1, nullptr, 1);  // -> g_a2 split

    // ---- layer 2 ----
    mma_gemm_k<768><<<dim3(4, NNP / 128), 256>>>(ga2, gbt2, gh, ghh, NN);
    asad_k<<<(NN * FH * 32 + 255) / 256, 256>>>(gh, atts2, attd2);
    agg_k<<<(NN * FH * 32 + 255) / 256, 256>>>(ghh, nullptr, gagg2, 0);

    // ---- tail ----
    final_k<<<(NN * 32 + 255) / 256, 256>>>(b2, Wout, bout, out);
}

// round 4
// speedup vs baseline: 1.1872x; 1.1173x over previous
#include <cuda_runtime.h>
#include <cuda_bf16.h>
#include <cuda_fp16.h>
#include <math.h>

#define NN 20000
#define NNP 20096        // padded to multiple of 128 for GEMM tiles
#define NE 640000
#define ET (NE + NN)     // edges + self loops = 660000
#define FH 4             // heads
#define CC 64            // channels per head
#define HC 256           // heads*channels

// ---------------- device scratch (no allocation allowed) ----------------
__device__ float g_h[NN * HC];      // transformed features fp32 (for attention logits)
__device__ __half g_hh[NN * HC];    // fp16 copy (for the per-edge gather)
__device__ float g_agg2[NN * HC];   // layer-2 aggregation [N,H,C]
__device__ float g_as[NN * FH];
__device__ float g_ad[NN * FH];
__device__ float g_e[FH * ET];      // per-edge leaky-relu logits, head-planes
__device__ int   g_deg[NN];
__device__ int   g_rowptr[NN + 1];
__device__ int   g_fill[NN];
__device__ int   g_csr_src[ET];
// bf16 split operands. A' = [Ah, Al, Ah] (K'=3K). BT[n][k'] with k' = [Bh, Bh, Bl].
__device__ __nv_bfloat16 g_a1[NNP * 384];
__device__ __nv_bfloat16 g_a2[NNP * 768];
__device__ __nv_bfloat16 g_bt1[256 * 384];
__device__ __nv_bfloat16 g_bt2[256 * 768];

// ---------------- CSR build ----------------
__global__ void zero_deg_k() {
    int i = blockIdx.x * blockDim.x + threadIdx.x;
    if (i < NN) g_deg[i] = 0;
}

#define QT ((ET + 3) / 4)
__global__ void hist_k(const int* __restrict__ ei) {
    int t = blockIdx.x * blockDim.x + threadIdx.x;
    if (t >= QT) return;
#pragma unroll
    for (int r = 0; r < 4; r++) {
        int e = t + r * QT;
        if (e < ET) {
            int dst = (e < NE) ? ei[NE + e] : (e - NE);
            atomicAdd(&g_deg[dst], 1);
        }
    }
}

__global__ void scan_k() {
    __shared__ int sm[1024];
    int tid = threadIdx.x;
    const int CH = 20;
    int base = tid * CH;
    int sum = 0;
#pragma unroll
    for (int i = 0; i < CH; i++) {
        int idx = base + i;
        if (idx < NN) sum += g_deg[idx];
    }
    sm[tid] = sum;
    __syncthreads();
    for (int off = 1; off < 1024; off <<= 1) {
        int v = (tid >= off) ? sm[tid - off] : 0;
        __syncthreads();
        sm[tid] += v;
        __syncthreads();
    }
    int run = sm[tid] - sum;
#pragma unroll
    for (int i = 0; i < CH; i++) {
        int idx = base + i;
        if (idx < NN) {
            g_rowptr[idx] = run;
            g_fill[idx] = run;
            run += g_deg[idx];
        }
    }
    if (tid == 0) g_rowptr[NN] = sm[1023];
}

__global__ void scatter_k(const int* __restrict__ ei) {
    int t = blockIdx.x * blockDim.x + threadIdx.x;
    if (t >= QT) return;
#pragma unroll
    for (int r = 0; r < 4; r++) {
        int e = t + r * QT;
        if (e < ET) {
            int src, dst;
            if (e < NE) { src = ei[e]; dst = ei[NE + e]; }
            else        { src = dst = e - NE; }
            int p = atomicAdd(&g_fill[dst], 1);
            g_csr_src[p] = src;
        }
    }
}

// ---------------- bf16 split prep ----------------
__global__ void split_x_k(const float* __restrict__ x) {
    int i = blockIdx.x * blockDim.x + threadIdx.x;
    if (i >= NN * 128) return;
    int m = i >> 7, j = i & 127;
    float v = x[i];
    __nv_bfloat16 h = __float2bfloat16(v);
    __nv_bfloat16 l = __float2bfloat16(v - __bfloat162float(h));
    g_a1[m * 384 + j] = h;
    g_a1[m * 384 + 128 + j] = l;
    g_a1[m * 384 + 256 + j] = h;
}

template <int K>
__global__ void split_w_k(const float* __restrict__ W, __nv_bfloat16* __restrict__ BT) {
    int i = blockIdx.x * blockDim.x + threadIdx.x;
    if (i >= K * 256) return;
    int r = i >> 8, c = i & 255;
    float v = W[i];
    __nv_bfloat16 h = __float2bfloat16(v);
    __nv_bfloat16 l = __float2bfloat16(v - __bfloat162float(h));
    BT[c * (3 * K) + r] = h;
    BT[c * (3 * K) + K + r] = h;
    BT[c * (3 * K) + 2 * K + r] = l;
}

// ---------------- pipelined tensor-core GEMM (mma.sync path) ----------------
__device__ __forceinline__ void mma_bf16(float* c, const unsigned* a, const unsigned* b) {
    asm volatile(
        "mma.sync.aligned.m16n8k16.row.col.f32.bf16.bf16.f32 "
        "{%0,%1,%2,%3}, {%4,%5,%6,%7}, {%8,%9}, {%0,%1,%2,%3};\n"
        : "+f"(c[0]), "+f"(c[1]), "+f"(c[2]), "+f"(c[3])
        : "r"(a[0]), "r"(a[1]), "r"(a[2]), "r"(a[3]), "r"(b[0]), "r"(b[1]));
}

template <int KP>
__global__ void mma_gemm_k(const __nv_bfloat16* __restrict__ A,
                           const __nv_bfloat16* __restrict__ BT,
                           float* __restrict__ C, __half* __restrict__ Ch, int M) {
    const int BM = 128, BN = 64, BK = 32, LD = 40;
    __shared__ __align__(16) __nv_bfloat16 As[2][BM * LD];
    __shared__ __align__(16) __nv_bfloat16 Bs[2][BN * LD];
    int t = threadIdx.x, lane = t & 31, wid = t >> 5;
    int wm = wid & 3, wn = wid >> 2;
    int bm = blockIdx.y * BM, bn = blockIdx.x * BN;
    float acc[2][4][4] = {};

    int ar = t >> 1, ac = (t & 1) * 16;
    int brow = t >> 2, bcol = (t & 3) * 8;

    auto load_tile = [&](int k0, int st) {
        const __nv_bfloat16* ag = A + (size_t)(bm + ar) * KP + k0 + ac;
        unsigned sa = (unsigned)__cvta_generic_to_shared(&As[st][ar * LD + ac]);
        asm volatile("cp.async.ca.shared.global [%0], [%1], 16;\n" :: "r"(sa), "l"(ag) : "memory");
        asm volatile("cp.async.ca.shared.global [%0], [%1], 16;\n" :: "r"(sa + 16), "l"(ag + 8) : "memory");
        const __nv_bfloat16* bg = BT + (size_t)(bn + brow) * KP + k0 + bcol;
        unsigned sb = (unsigned)__cvta_generic_to_shared(&Bs[st][brow * LD + bcol]);
        asm volatile("cp.async.ca.shared.global [%0], [%1], 16;\n" :: "r"(sb), "l"(bg) : "memory");
        asm volatile("cp.async.commit_group;\n" ::: "memory");
    };

    load_tile(0, 0);
    const int NT = KP / BK;
    for (int i = 0; i < NT; i++) {
        if (i + 1 < NT) {
            load_tile((i + 1) * BK, (i + 1) & 1);
            asm volatile("cp.async.wait_group 1;\n" ::: "memory");
        } else {
            asm volatile("cp.async.wait_group 0;\n" ::: "memory");
        }
        __syncthreads();
        int st = i & 1;
#pragma unroll
        for (int kk = 0; kk < BK; kk += 16) {
            unsigned af[2][4], bf[2][4];
#pragma unroll
            for (int mt = 0; mt < 2; mt++) {
                unsigned addr = (unsigned)__cvta_generic_to_shared(
                    &As[st][(wm * 32 + mt * 16 + (lane & 15)) * LD + kk + (lane >> 4) * 8]);
                asm volatile("ldmatrix.sync.aligned.m8n8.x4.shared.b16 {%0,%1,%2,%3}, [%4];\n"
                             : "=r"(af[mt][0]), "=r"(af[mt][1]), "=r"(af[mt][2]), "=r"(af[mt][3])
                             : "r"(addr));
            }
#pragma unroll
            for (int nb = 0; nb < 2; nb++) {
                int nr = wn * 32 + nb * 16 + (lane & 7) + ((lane >> 4) << 3);
                int kc = kk + ((lane >> 3) & 1) * 8;
                unsigned addr = (unsigned)__cvta_generic_to_shared(&Bs[st][nr * LD + kc]);
                asm volatile("ldmatrix.sync.aligned.m8n8.x4.shared.b16 {%0,%1,%2,%3}, [%4];\n"
                             : "=r"(bf[nb][0]), "=r"(bf[nb][1]), "=r"(bf[nb][2]), "=r"(bf[nb][3])
                             : "r"(addr));
            }
#pragma unroll
            for (int mt = 0; mt < 2; mt++)
#pragma unroll
                for (int nt = 0; nt < 4; nt++) {
                    unsigned bq[2] = { bf[nt >> 1][(nt & 1) * 2], bf[nt >> 1][(nt & 1) * 2 + 1] };
                    mma_bf16(acc[mt][nt], af[mt], bq);
                }
        }
        __syncthreads();
    }

    int g = lane >> 2, tg = lane & 3;
#pragma unroll
    for (int mt = 0; mt < 2; mt++) {
        int r0 = bm + wm * 32 + mt * 16 + g;
#pragma unroll
        for (int nt = 0; nt < 4; nt++) {
            int c = bn + wn * 32 + nt * 8 + tg * 2;
            if (r0 < M) {
                *(float2*)&C[(size_t)r0 * 256 + c] = make_float2(acc[mt][nt][0], acc[mt][nt][1]);
                *(__half2*)&Ch[(size_t)r0 * 256 + c] = __floats2half2_rn(acc[mt][nt][0], acc[mt][nt][1]);
            }
            if (r0 + 8 < M) {
                *(float2*)&C[(size_t)(r0 + 8) * 256 + c] = make_float2(acc[mt][nt][2], acc[mt][nt][3]);
                *(__half2*)&Ch[(size_t)(r0 + 8) * 256 + c] = __floats2half2_rn(acc[mt][nt][2], acc[mt][nt][3]);
            }
        }
    }
}

// ---------------- per-(node,head) attention coefficients ----------------
__global__ void asad_k(const float* __restrict__ h, const float* __restrict__ atts,
                       const float* __restrict__ attd) {
    int warp = (blockIdx.x * blockDim.x + threadIdx.x) >> 5;
    int lane = threadIdx.x & 31;
    if (warp >= NN * FH) return;
    int n = warp >> 2, hd = warp & 3;
    float2 hv = *(const float2*)&h[n * HC + hd * CC + 2 * lane];
    float2 sv = *(const float2*)&atts[hd * CC + 2 * lane];
    float2 dv = *(const float2*)&attd[hd * CC + 2 * lane];
    float ps = hv.x * sv.x + hv.y * sv.y;
    float pd = hv.x * dv.x + hv.y * dv.y;
#pragma unroll
    for (int off = 16; off; off >>= 1) {
        ps += __shfl_xor_sync(0xffffffffu, ps, off);
        pd += __shfl_xor_sync(0xffffffffu, pd, off);
    }
    if (lane == 0) { g_as[warp] = ps; g_ad[warp] = pd; }
}

// ---------------- per-edge logits: e[hd][i] = leaky(as[src]+ad[dst]) ----------------
__global__ void edge_e_k() {
    int warp = (blockIdx.x * blockDim.x + threadIdx.x) >> 5;
    int lane = threadIdx.x & 31;
    if (warp >= NN) return;
    int n = warp;
    int beg = g_rowptr[n], end = g_rowptr[n + 1];
    float4 ad4 = *(const float4*)&g_ad[n * FH];
    for (int i = beg + lane; i < end; i += 32) {
        int sc = g_csr_src[i];
        float4 s4 = *(const float4*)&g_as[sc * FH];
        float e0 = s4.x + ad4.x; e0 = (e0 > 0.f) ? e0 : 0.2f * e0;
        float e1 = s4.y + ad4.y; e1 = (e1 > 0.f) ? e1 : 0.2f * e1;
        float e2 = s4.z + ad4.z; e2 = (e2 > 0.f) ? e2 : 0.2f * e2;
        float e3 = s4.w + ad4.w; e3 = (e3 > 0.f) ? e3 : 0.2f * e3;
        g_e[0 * ET + i] = e0;
        g_e[1 * ET + i] = e1;
        g_e[2 * ET + i] = e2;
        g_e[3 * ET + i] = e3;
    }
}

// ---------------- GAT aggregation: one warp per (dst,head) ----------------
__global__ void agg_k(const __half* __restrict__ hh, const float* __restrict__ bias,
                      float* __restrict__ outf, int layer1) {
    int task = (blockIdx.x * blockDim.x + threadIdx.x) >> 5;
    int lane = threadIdx.x & 31;
    if (task >= NN * FH) return;
    int n = task >> 2, hd = task & 3;
    int beg = g_rowptr[n], end = g_rowptr[n + 1];
    const float* ep = g_e + hd * ET;

    // pass 1: softmax stats over coalesced logits
    float m = -1e30f, s = 0.f;
    for (int i = beg + lane; i < end; i += 32) {
        float e = ep[i];
        float mn = fmaxf(m, e);
        s = s * __expf(m - mn) + __expf(e - mn);
        m = mn;
    }
#pragma unroll
    for (int off = 16; off; off >>= 1) {
        float mo = __shfl_xor_sync(0xffffffffu, m, off);
        float so = __shfl_xor_sync(0xffffffffu, s, off);
        float mn = fmaxf(m, mo);
        s = s * __expf(m - mn) + so * __expf(mo - mn);
        m = mn;
    }
    float inv = 1.f / s;

    // pass 2: lane-batched alpha/src, shfl-distributed gather
    int c0 = 2 * lane;
    const __half* hp = hh + hd * CC + c0;
    float a0 = 0.f, a1 = 0.f;
    for (int base = beg; base < end; base += 32) {
        int i = base + lane;
        float al = 0.f; int sj = 0;
        if (i < end) {
            al = __expf(ep[i] - m) * inv;
            sj = g_csr_src[i];
        }
        int cnt = end - base;
        if (cnt >= 32) {
#pragma unroll 8
            for (int j = 0; j < 32; j++) {
                float a = __shfl_sync(0xffffffffu, al, j);
                int sc = __shfl_sync(0xffffffffu, sj, j);
                float2 hv = __half22float2(*(const __half2*)(hp + sc * HC));
                a0 += a * hv.x;
                a1 += a * hv.y;
            }
        } else {
            for (int j = 0; j < cnt; j++) {
                float a = __shfl_sync(0xffffffffu, al, j);
                int sc = __shfl_sync(0xffffffffu, sj, j);
                float2 hv = __half22float2(*(const __half2*)(hp + sc * HC));
                a0 += a * hv.x;
                a1 += a * hv.y;
            }
        }
    }
    int j = hd * CC + c0;
    if (layer1) {
        float v0 = a0 + bias[j];
        float v1 = a1 + bias[j + 1];
        v0 = (v0 > 0.f) ? v0 : (__expf(v0) - 1.f);   // elu
        v1 = (v1 > 0.f) ? v1 : (__expf(v1) - 1.f);
        __nv_bfloat16 h0 = __float2bfloat16(v0), h1 = __float2bfloat16(v1);
        __nv_bfloat16 l0 = __float2bfloat16(v0 - __bfloat162float(h0));
        __nv_bfloat16 l1 = __float2bfloat16(v1 - __bfloat162float(h1));
        __nv_bfloat162 hi2; hi2.x = h0; hi2.y = h1;
        __nv_bfloat162 lo2; lo2.x = l0; lo2.y = l1;
        *(__nv_bfloat162*)&g_a2[n * 768 + j]       = hi2;
        *(__nv_bfloat162*)&g_a2[n * 768 + 256 + j] = lo2;
        *(__nv_bfloat162*)&g_a2[n * 768 + 512 + j] = hi2;
    } else {
        outf[n * HC + j] = a0;
        outf[n * HC + j + 1] = a1;
    }
}

// ---------------- tail: head-mean + b2, then @Wout + bout ----------------
__global__ void final_k(const float* __restrict__ b2, const float* __restrict__ Wout,
                        const float* __restrict__ bout, float* __restrict__ out) {
    __shared__ float Ws[CC * 16];
    int t = threadIdx.x;
    for (int i = t; i < CC * 16; i += blockDim.x) Ws[i] = Wout[i];
    __syncthreads();
    int warp = (blockIdx.x * blockDim.x + t) >> 5;
    int lane = t & 31;
    if (warp >= NN) return;
    int n = warp;
    int c0 = 2 * lane;
    float v0 = 0.f, v1 = 0.f;
#pragma unroll
    for (int hd = 0; hd < FH; hd++) {
        float2 hv = *(const float2*)&g_agg2[n * HC + hd * CC + c0];
        v0 += hv.x; v1 += hv.y;
    }
    v0 = v0 * 0.25f + b2[c0];
    v1 = v1 * 0.25f + b2[c0 + 1];
    float p[16];
#pragma unroll
    for (int k = 0; k < 16; k++)
        p[k] = v0 * Ws[c0 * 16 + k] + v1 * Ws[(c0 + 1) * 16 + k];
#pragma unroll
    for (int k = 0; k < 16; k++) {
#pragma unroll
        for (int off = 16; off; off >>= 1)
            p[k] += __shfl_xor_sync(0xffffffffu, p[k], off);
    }
    if (lane < 16) out[n * 16 + lane] = p[lane] + bout[lane];
}

// ---------------- launch ----------------
extern "C" void kernel_launch(void* const* d_in, const int* in_sizes, int n_in,
                              void* d_out, int out_size) {
    const float* x     = (const float*)d_in[0];
    const int*   ei    = (const int*)d_in[1];
    const float* W1    = (const float*)d_in[2];
    const float* atts1 = (const float*)d_in[3];
    const float* attd1 = (const float*)d_in[4];
    const float* b1    = (const float*)d_in[5];
    const float* W2    = (const float*)d_in[6];
    const float* atts2 = (const float*)d_in[7];
    const float* attd2 = (const float*)d_in[8];
    const float* b2    = (const float*)d_in[9];
    const float* Wout  = (const float*)d_in[10];
    const float* bout  = (const float*)d_in[11];
    float* out = (float*)d_out;

    float* gh;    cudaGetSymbolAddress((void**)&gh, g_h);
    __half* ghh;  cudaGetSymbolAddress((void**)&ghh, g_hh);
    float* gagg2; cudaGetSymbolAddress((void**)&gagg2, g_agg2);
    __nv_bfloat16 *ga1, *ga2, *gbt1, *gbt2;
    cudaGetSymbolAddress((void**)&ga1, g_a1);
    cudaGetSymbolAddress((void**)&ga2, g_a2);
    cudaGetSymbolAddress((void**)&gbt1, g_bt1);
    cudaGetSymbolAddress((void**)&gbt2, g_bt2);

    // prep + layer-1 GEMM first (so the profiler's skip-N lands on the GEMM)
    split_x_k<<<(NN * 128 + 255) / 256, 256>>>(x);
    split_w_k<128><<<(128 * 256 + 255) / 256, 256>>>(W1, gbt1);
    split_w_k<256><<<(256 * 256 + 255) / 256, 256>>>(W2, gbt2);
    mma_gemm_k<384><<<dim3(4, NNP / 128), 256>>>(ga1, gbt1, gh, ghh, NN);

    // CSR build (independent of GEMM)
    zero_deg_k<<<(NN + 255) / 256, 256>>>();
    hist_k<<<(QT + 255) / 256, 256>>>(ei);
    scan_k<<<1, 1024>>>();
    scatter_k<<<(QT + 255) / 256, 256>>>(ei);

    // ---- layer 1 attention ----
    asad_k<<<(NN * FH * 32 + 255) / 256, 256>>>(gh, atts1, attd1);
    edge_e_k<<<(NN * 32 + 255) / 256, 256>>>();
    agg_k<<<(NN * FH * 32 + 255) / 256, 256>>>(ghh, b1, nullptr, 1);

    // ---- layer 2 ----
    mma_gemm_k<768><<<dim3(4, NNP / 128), 256>>>(ga2, gbt2, gh, ghh, NN);
    asad_k<<<(NN * FH * 32 + 255) / 256, 256>>>(gh, atts2, attd2);
    edge_e_k<<<(NN * 32 + 255) / 256, 256>>>();
    agg_k<<<(NN * FH * 32 + 255) / 256, 256>>>(ghh, nullptr, gagg2, 0);

    // ---- tail ----
    final_k<<<(NN * 32 + 255) / 256, 256>>>(b2, Wout, bout, out);
}

// round 5
// speedup vs baseline: 1.4127x; 1.1899x over previous
#include <cuda_runtime.h>
#include <cuda_bf16.h>
#include <cuda_fp16.h>
#include <math.h>

#define NN 20000
#define NNP 20096        // padded to multiple of 128 for GEMM tiles
#define NE 640000
#define ET (NE + NN)     // edges + self loops = 660000
#define FH 4             // heads
#define CC 64            // channels per head
#define HC 256           // heads*channels

// ---------------- device scratch (no allocation allowed) ----------------
__device__ float  g_h[NN * HC];      // transformed features fp32 (attention logits)
__device__ __half g_hh[NN * HC];     // fp16 copy (per-edge gather)
__device__ __half g_xh[NNP * 128];   // fp16 input x (layer-1 GEMM A)
__device__ __half g_x2h[NNP * HC];   // fp16 elu(agg1+b1) (layer-2 GEMM A)
__device__ float  g_agg2[NN * HC];   // layer-2 aggregation
__device__ float  g_as[NN * FH];
__device__ float  g_ad[NN * FH];
__device__ float  g_e[FH * ET];      // per-edge leaky logits, head planes
__device__ float  g_m[NN * FH];      // softmax max
__device__ float  g_inv[NN * FH];    // softmax 1/sum
__device__ int    g_deg[NN];
__device__ int    g_rowptr[NN + 1];
__device__ int    g_fill[NN];
__device__ int    g_csr_src[ET];
__device__ __half g_bt1[256 * 128];  // W1^T fp16: [out col][k]
__device__ __half g_bt2[256 * 256];  // W2^T fp16

// ---------------- prep ----------------
__global__ void cvt_x_k(const float* __restrict__ x) {
    int i = blockIdx.x * blockDim.x + threadIdx.x;
    if (i >= NN * 128) return;
    int m = i >> 7, j = i & 127;
    g_xh[m * 128 + j] = __float2half(x[i]);
}

template <int K>
__global__ void wt_k(const float* __restrict__ W, __half* __restrict__ BT) {
    int i = blockIdx.x * blockDim.x + threadIdx.x;
    if (i >= K * 256) return;
    int r = i >> 8, c = i & 255;
    BT[c * K + r] = __float2half(W[i]);
}

// ---------------- CSR build ----------------
__global__ void zero_deg_k() {
    int i = blockIdx.x * blockDim.x + threadIdx.x;
    if (i < NN) g_deg[i] = 0;
}

#define QT ((ET + 3) / 4)
__global__ void hist_k(const int* __restrict__ ei) {
    int t = blockIdx.x * blockDim.x + threadIdx.x;
    if (t >= QT) return;
#pragma unroll
    for (int r = 0; r < 4; r++) {
        int e = t + r * QT;
        if (e < ET) {
            int dst = (e < NE) ? ei[NE + e] : (e - NE);
            atomicAdd(&g_deg[dst], 1);
        }
    }
}

__global__ void scan_k() {
    __shared__ int sm[1024];
    int tid = threadIdx.x;
    const int CH = 20;
    int base = tid * CH;
    int sum = 0;
#pragma unroll
    for (int i = 0; i < CH; i++) {
        int idx = base + i;
        if (idx < NN) sum += g_deg[idx];
    }
    sm[tid] = sum;
    __syncthreads();
    for (int off = 1; off < 1024; off <<= 1) {
        int v = (tid >= off) ? sm[tid - off] : 0;
        __syncthreads();
        sm[tid] += v;
        __syncthreads();
    }
    int run = sm[tid] - sum;
#pragma unroll
    for (int i = 0; i < CH; i++) {
        int idx = base + i;
        if (idx < NN) {
            g_rowptr[idx] = run;
            g_fill[idx] = run;
            run += g_deg[idx];
        }
    }
    if (tid == 0) g_rowptr[NN] = sm[1023];
}

__global__ void scatter_k(const int* __restrict__ ei) {
    int t = blockIdx.x * blockDim.x + threadIdx.x;
    if (t >= QT) return;
#pragma unroll
    for (int r = 0; r < 4; r++) {
        int e = t + r * QT;
        if (e < ET) {
            int src, dst;
            if (e < NE) { src = ei[e]; dst = ei[NE + e]; }
            else        { src = dst = e - NE; }
            int p = atomicAdd(&g_fill[dst], 1);
            g_csr_src[p] = src;
        }
    }
}

// ---------------- pipelined fp16 tensor-core GEMM ----------------
__device__ __forceinline__ void mma_f16(float* c, const unsigned* a, const unsigned* b) {
    asm volatile(
        "mma.sync.aligned.m16n8k16.row.col.f32.f16.f16.f32 "
        "{%0,%1,%2,%3}, {%4,%5,%6,%7}, {%8,%9}, {%0,%1,%2,%3};\n"
        : "+f"(c[0]), "+f"(c[1]), "+f"(c[2]), "+f"(c[3])
        : "r"(a[0]), "r"(a[1]), "r"(a[2]), "r"(a[3]), "r"(b[0]), "r"(b[1]));
}

template <int KP>
__global__ void mma_gemm_k(const __half* __restrict__ A,
                           const __half* __restrict__ BT,
                           float* __restrict__ C, __half* __restrict__ Ch, int M) {
    const int BM = 128, BN = 64, BK = 32, LD = 40;
    __shared__ __align__(16) __half As[2][BM * LD];
    __shared__ __align__(16) __half Bs[2][BN * LD];
    int t = threadIdx.x, lane = t & 31, wid = t >> 5;
    int wm = wid & 3, wn = wid >> 2;
    int bm = blockIdx.y * BM, bn = blockIdx.x * BN;
    float acc[2][4][4] = {};

    int ar = t >> 1, ac = (t & 1) * 16;
    int brow = t >> 2, bcol = (t & 3) * 8;

    auto load_tile = [&](int k0, int st) {
        const __half* ag = A + (size_t)(bm + ar) * KP + k0 + ac;
        unsigned sa = (unsigned)__cvta_generic_to_shared(&As[st][ar * LD + ac]);
        asm volatile("cp.async.ca.shared.global [%0], [%1], 16;\n" :: "r"(sa), "l"(ag) : "memory");
        asm volatile("cp.async.ca.shared.global [%0], [%1], 16;\n" :: "r"(sa + 16), "l"(ag + 8) : "memory");
        const __half* bg = BT + (size_t)(bn + brow) * KP + k0 + bcol;
        unsigned sb = (unsigned)__cvta_generic_to_shared(&Bs[st][brow * LD + bcol]);
        asm volatile("cp.async.ca.shared.global [%0], [%1], 16;\n" :: "r"(sb), "l"(bg) : "memory");
        asm volatile("cp.async.commit_group;\n" ::: "memory");
    };

    load_tile(0, 0);
    const int NT = KP / BK;
    for (int i = 0; i < NT; i++) {
        if (i + 1 < NT) {
            load_tile((i + 1) * BK, (i + 1) & 1);
            asm volatile("cp.async.wait_group 1;\n" ::: "memory");
        } else {
            asm volatile("cp.async.wait_group 0;\n" ::: "memory");
        }
        __syncthreads();
        int st = i & 1;
#pragma unroll
        for (int kk = 0; kk < BK; kk += 16) {
            unsigned af[2][4], bf[2][4];
#pragma unroll
            for (int mt = 0; mt < 2; mt++) {
                unsigned addr = (unsigned)__cvta_generic_to_shared(
                    &As[st][(wm * 32 + mt * 16 + (lane & 15)) * LD + kk + (lane >> 4) * 8]);
                asm volatile("ldmatrix.sync.aligned.m8n8.x4.shared.b16 {%0,%1,%2,%3}, [%4];\n"
                             : "=r"(af[mt][0]), "=r"(af[mt][1]), "=r"(af[mt][2]), "=r"(af[mt][3])
                             : "r"(addr));
            }
#pragma unroll
            for (int nb = 0; nb < 2; nb++) {
                int nr = wn * 32 + nb * 16 + (lane & 7) + ((lane >> 4) << 3);
                int kc = kk + ((lane >> 3) & 1) * 8;
                unsigned addr = (unsigned)__cvta_generic_to_shared(&Bs[st][nr * LD + kc]);
                asm volatile("ldmatrix.sync.aligned.m8n8.x4.shared.b16 {%0,%1,%2,%3}, [%4];\n"
                             : "=r"(bf[nb][0]), "=r"(bf[nb][1]), "=r"(bf[nb][2]), "=r"(bf[nb][3])
                             : "r"(addr));
            }
#pragma unroll
            for (int mt = 0; mt < 2; mt++)
#pragma unroll
                for (int nt = 0; nt < 4; nt++) {
                    unsigned bq[2] = { bf[nt >> 1][(nt & 1) * 2], bf[nt >> 1][(nt & 1) * 2 + 1] };
                    mma_f16(acc[mt][nt], af[mt], bq);
                }
        }
        __syncthreads();
    }

    int g = lane >> 2, tg = lane & 3;
#pragma unroll
    for (int mt = 0; mt < 2; mt++) {
        int r0 = bm + wm * 32 + mt * 16 + g;
#pragma unroll
        for (int nt = 0; nt < 4; nt++) {
            int c = bn + wn * 32 + nt * 8 + tg * 2;
            if (r0 < M) {
                *(float2*)&C[(size_t)r0 * 256 + c] = make_float2(acc[mt][nt][0], acc[mt][nt][1]);
                *(__half2*)&Ch[(size_t)r0 * 256 + c] = __floats2half2_rn(acc[mt][nt][0], acc[mt][nt][1]);
            }
            if (r0 + 8 < M) {
                *(float2*)&C[(size_t)(r0 + 8) * 256 + c] = make_float2(acc[mt][nt][2], acc[mt][nt][3]);
                *(__half2*)&Ch[(size_t)(r0 + 8) * 256 + c] = __floats2half2_rn(acc[mt][nt][2], acc[mt][nt][3]);
            }
        }
    }
}

// ---------------- per-(node,head) attention coefficients ----------------
__global__ void asad_k(const float* __restrict__ h, const float* __restrict__ atts,
                       const float* __restrict__ attd) {
    int warp = (blockIdx.x * blockDim.x + threadIdx.x) >> 5;
    int lane = threadIdx.x & 31;
    if (warp >= NN * FH) return;
    int n = warp >> 2, hd = warp & 3;
    float2 hv = *(const float2*)&h[n * HC + hd * CC + 2 * lane];
    float2 sv = *(const float2*)&atts[hd * CC + 2 * lane];
    float2 dv = *(const float2*)&attd[hd * CC + 2 * lane];
    float ps = hv.x * sv.x + hv.y * sv.y;
    float pd = hv.x * dv.x + hv.y * dv.y;
#pragma unroll
    for (int off = 16; off; off >>= 1) {
        ps += __shfl_xor_sync(0xffffffffu, ps, off);
        pd += __shfl_xor_sync(0xffffffffu, pd, off);
    }
    if (lane == 0) { g_as[warp] = ps; g_ad[warp] = pd; }
}

// ---------------- per-edge logits + fused softmax stats ----------------
// one warp per dst node; computes e for all 4 heads, plus per-head (max, 1/sum)
__global__ void edge_e_k() {
    int warp = (blockIdx.x * blockDim.x + threadIdx.x) >> 5;
    int lane = threadIdx.x & 31;
    if (warp >= NN) return;
    int n = warp;
    int beg = g_rowptr[n], end = g_rowptr[n + 1];
    float4 ad4 = *(const float4*)&g_ad[n * FH];
    float m[4] = {-1e30f, -1e30f, -1e30f, -1e30f};
    float s[4] = {0.f, 0.f, 0.f, 0.f};
    for (int i = beg + lane; i < end; i += 32) {
        int sc = g_csr_src[i];
        float4 s4 = *(const float4*)&g_as[sc * FH];
        float e[4];
        e[0] = s4.x + ad4.x; e[1] = s4.y + ad4.y;
        e[2] = s4.z + ad4.z; e[3] = s4.w + ad4.w;
#pragma unroll
        for (int hdv = 0; hdv < 4; hdv++) {
            float ev = e[hdv];
            ev = (ev > 0.f) ? ev : 0.2f * ev;
            g_e[hdv * ET + i] = ev;
            float mn = fmaxf(m[hdv], ev);
            s[hdv] = s[hdv] * __expf(m[hdv] - mn) + __expf(ev - mn);
            m[hdv] = mn;
        }
    }
#pragma unroll
    for (int hdv = 0; hdv < 4; hdv++) {
#pragma unroll
        for (int off = 16; off; off >>= 1) {
            float mo = __shfl_xor_sync(0xffffffffu, m[hdv], off);
            float so = __shfl_xor_sync(0xffffffffu, s[hdv], off);
            float mn = fmaxf(m[hdv], mo);
            s[hdv] = s[hdv] * __expf(m[hdv] - mn) + so * __expf(mo - mn);
            m[hdv] = mn;
        }
    }
    if (lane == 0) {
#pragma unroll
        for (int hdv = 0; hdv < 4; hdv++) {
            g_m[n * FH + hdv] = m[hdv];
            g_inv[n * FH + hdv] = 1.f / s[hdv];
        }
    }
}

// ---------------- GAT aggregation: one warp per (dst,head), single pass ----------------
__global__ void agg_k(const __half* __restrict__ hh, const float* __restrict__ bias,
                      float* __restrict__ outf, int layer1) {
    int task = (blockIdx.x * blockDim.x + threadIdx.x) >> 5;
    int lane = threadIdx.x & 31;
    if (task >= NN * FH) return;
    int n = task >> 2, hd = task & 3;
    int beg = g_rowptr[n], end = g_rowptr[n + 1];
    const float* ep = g_e + hd * ET;
    float m = g_m[n * FH + hd];
    float inv = g_inv[n * FH + hd];

    int c0 = 2 * lane;
    const __half* hp = hh + hd * CC + c0;
    float a0 = 0.f, a1 = 0.f;
    for (int base = beg; base < end; base += 32) {
        int i = base + lane;
        float al = 0.f; int sj = 0;
        if (i < end) {
            al = __expf(ep[i] - m) * inv;
            sj = g_csr_src[i];
        }
        int cnt = end - base;
        if (cnt >= 32) {
#pragma unroll 8
            for (int j = 0; j < 32; j++) {
                float a = __shfl_sync(0xffffffffu, al, j);
                int sc = __shfl_sync(0xffffffffu, sj, j);
                float2 hv = __half22float2(*(const __half2*)(hp + sc * HC));
                a0 += a * hv.x;
                a1 += a * hv.y;
            }
        } else {
            for (int j = 0; j < cnt; j++) {
                float a = __shfl_sync(0xffffffffu, al, j);
                int sc = __shfl_sync(0xffffffffu, sj, j);
                float2 hv = __half22float2(*(const __half2*)(hp + sc * HC));
                a0 += a * hv.x;
                a1 += a * hv.y;
            }
        }
    }
    int j = hd * CC + c0;
    if (layer1) {
        float v0 = a0 + bias[j];
        float v1 = a1 + bias[j + 1];
        v0 = (v0 > 0.f) ? v0 : (__expf(v0) - 1.f);   // elu
        v1 = (v1 > 0.f) ? v1 : (__expf(v1) - 1.f);
        *(__half2*)&g_x2h[n * HC + j] = __floats2half2_rn(v0, v1);
    } else {
        outf[n * HC + j] = a0;
        outf[n * HC + j + 1] = a1;
    }
}

// ---------------- tail: head-mean + b2, then @Wout + bout ----------------
__global__ void final_k(const float* __restrict__ b2, const float* __restrict__ Wout,
                        const float* __restrict__ bout, float* __restrict__ out) {
    __shared__ float Ws[CC * 16];
    int t = threadIdx.x;
    for (int i = t; i < CC * 16; i += blockDim.x) Ws[i] = Wout[i];
    __syncthreads();
    int warp = (blockIdx.x * blockDim.x + t) >> 5;
    int lane = t & 31;
    if (warp >= NN) return;
    int n = warp;
    int c0 = 2 * lane;
    float v0 = 0.f, v1 = 0.f;
#pragma unroll
    for (int hd = 0; hd < FH; hd++) {
        float2 hv = *(const float2*)&g_agg2[n * HC + hd * CC + c0];
        v0 += hv.x; v1 += hv.y;
    }
    v0 = v0 * 0.25f + b2[c0];
    v1 = v1 * 0.25f + b2[c0 + 1];
    float p[16];
#pragma unroll
    for (int k = 0; k < 16; k++)
        p[k] = v0 * Ws[c0 * 16 + k] + v1 * Ws[(c0 + 1) * 16 + k];
#pragma unroll
    for (int k = 0; k < 16; k++) {
#pragma unroll
        for (int off = 16; off; off >>= 1)
            p[k] += __shfl_xor_sync(0xffffffffu, p[k], off);
    }
    if (lane < 16) out[n * 16 + lane] = p[lane] + bout[lane];
}

// ---------------- launch ----------------
extern "C" void kernel_launch(void* const* d_in, const int* in_sizes, int n_in,
                              void* d_out, int out_size) {
    const float* x     = (const float*)d_in[0];
    const int*   ei    = (const int*)d_in[1];
    const float* W1    = (const float*)d_in[2];
    const float* atts1 = (const float*)d_in[3];
    const float* attd1 = (const float*)d_in[4];
    const float* b1    = (const float*)d_in[5];
    const float* W2    = (const float*)d_in[6];
    const float* atts2 = (const float*)d_in[7];
    const float* attd2 = (const float*)d_in[8];
    const float* b2    = (const float*)d_in[9];
    const float* Wout  = (const float*)d_in[10];
    const float* bout  = (const float*)d_in[11];
    float* out = (float*)d_out;

    float*  gh;    cudaGetSymbolAddress((void**)&gh, g_h);
    __half* ghh;   cudaGetSymbolAddress((void**)&ghh, g_hh);
    __half* gxh;   cudaGetSymbolAddress((void**)&gxh, g_xh);
    __half* gx2h;  cudaGetSymbolAddress((void**)&gx2h, g_x2h);
    float*  gagg2; cudaGetSymbolAddress((void**)&gagg2, g_agg2);
    __half* gbt1;  cudaGetSymbolAddress((void**)&gbt1, g_bt1);
    __half* gbt2;  cudaGetSymbolAddress((void**)&gbt2, g_bt2);

    // prep + layer-1 GEMM first (profiler lands on the GEMM)
    cvt_x_k<<<(NN * 128 + 255) / 256, 256>>>(x);
    wt_k<128><<<(128 * 256 + 255) / 256, 256>>>(W1, gbt1);
    wt_k<256><<<(256 * 256 + 255) / 256, 256>>>(W2, gbt2);
    mma_gemm_k<128><<<dim3(4, NNP / 128), 256>>>(gxh, gbt1, gh, ghh, NN);

    // CSR build
    zero_deg_k<<<(NN + 255) / 256, 256>>>();
    hist_k<<<(QT + 255) / 256, 256>>>(ei);
    scan_k<<<1, 1024>>>();
    scatter_k<<<(QT + 255) / 256, 256>>>(ei);

    // ---- layer 1 attention ----
    asad_k<<<(NN * FH * 32 + 255) / 256, 256>>>(gh, atts1, attd1);
    edge_e_k<<<(NN * 32 + 255) / 256, 256>>>();
    agg_k<<<(NN * FH * 32 + 255) / 256, 256>>>(ghh, b1, nullptr, 1);

    // ---- layer 2 ----
    mma_gemm_k<256><<<dim3(4, NNP / 128), 256>>>(gx2h, gbt2, gh, ghh, NN);
    asad_k<<<(NN * FH * 32 + 255) / 256, 256>>>(gh, atts2, attd2);
    edge_e_k<<<(NN * 32 + 255) / 256, 256>>>();
    agg_k<<<(NN * FH * 32 + 255) / 256, 256>>>(ghh, nullptr, gagg2, 0);

    // ---- tail ----
    final_k<<<(NN * 32 + 255) / 256, 256>>>(b2, Wout, bout, out);
}

// round 6
// speedup vs baseline: 1.5942x; 1.1285x over previous
#include <cuda_runtime.h>
#include <cuda_bf16.h>
#include <cuda_fp16.h>
#include <math.h>

#define NN 20000
#define NNP 20096        // padded to multiple of 128 for GEMM tiles
#define NE 640000
#define ET (NE + NN)     // edges + self loops
#define FH 4
#define CC 64
#define HC 256

// ---------------- device scratch ----------------
__device__ __half g_hh[NN * HC];     // transformed features fp16 (edge gather)
__device__ __half g_xh[NNP * 128];   // fp16 x (layer-1 GEMM A)
__device__ __half g_x2h[NNP * HC];   // fp16 elu(agg1+b1) (layer-2 GEMM A)
__device__ float  g_agg2[NN * HC];
__device__ float  g_as[NN * FH];
__device__ float  g_ad[NN * FH];
__device__ int    g_gmax1[FH];       // encoded global max of as, layer 1
__device__ int    g_gmax2[FH];
__device__ int    g_deg[NN];
__device__ int    g_rowptr[NN + 1];
__device__ int    g_fill[NN];
__device__ int    g_csr_src[ET];
__device__ __half g_bt1[256 * 128];  // W1^T fp16
__device__ __half g_bt2[256 * 256];  // W2^T fp16
__device__ float  g_wsd1[8 * 128];   // [j][k]: j<4 -> W1*att_s head j ; j>=4 -> att_d
__device__ float  g_wsd2[8 * 256];

// monotone float<->int encode for atomicMax over signed floats
__device__ __forceinline__ int enc_f(float f) {
    int i = __float_as_int(f);
    return i >= 0 ? i : (i ^ 0x7FFFFFFF);
}
__device__ __forceinline__ float dec_f(int u) {
    return __int_as_float(u >= 0 ? u : (u ^ 0x7FFFFFFF));
}

// ---------------- prep ----------------
__global__ void cvt_x_k(const float* __restrict__ x) {
    int i = blockIdx.x * blockDim.x + threadIdx.x;
    if (i >= NN * 128) return;
    g_xh[(i >> 7) * 128 + (i & 127)] = __float2half(x[i]);
}

template <int K>
__global__ void wt_k(const float* __restrict__ W, __half* __restrict__ BT) {
    int i = blockIdx.x * blockDim.x + threadIdx.x;
    if (i >= K * 256) return;
    int r = i >> 8, c = i & 255;
    BT[c * K + r] = __float2half(W[i]);
}

// Wsd[j][k] = sum_c W[k, (j&3)*64+c] * att[(j&3)][c]
__global__ void wsd_k(const float* __restrict__ W, const float* __restrict__ atts,
                      const float* __restrict__ attd, float* __restrict__ wsdt,
                      int K, int doInit) {
    int t = blockIdx.x * blockDim.x + threadIdx.x;
    if (doInit && t < 8) {
        if (t < 4) g_gmax1[t] = (int)0x80000000;
        else       g_gmax2[t - 4] = (int)0x80000000;
    }
    if (t >= 8 * K) return;
    int j = t / K, k = t - j * K;
    int hd = j & 3;
    const float* av = (j < 4 ? atts : attd) + hd * 64;
    const float* wr = W + k * 256 + hd * 64;
    float s = 0.f;
#pragma unroll 16
    for (int c = 0; c < 64; c++) s += wr[c] * av[c];
    wsdt[j * K + k] = s;
}

// ---------------- CSR build ----------------
__global__ void zero_deg_k() {
    int i = blockIdx.x * blockDim.x + threadIdx.x;
    if (i < NN) g_deg[i] = 0;
}

#define QT ((ET + 3) / 4)
__global__ void hist_k(const int* __restrict__ ei) {
    int t = blockIdx.x * blockDim.x + threadIdx.x;
    if (t >= QT) return;
#pragma unroll
    for (int r = 0; r < 4; r++) {
        int e = t + r * QT;
        if (e < ET) {
            int dst = (e < NE) ? ei[NE + e] : (e - NE);
            atomicAdd(&g_deg[dst], 1);
        }
    }
}

__global__ void scan_k() {
    __shared__ int sm[1024];
    int tid = threadIdx.x;
    const int CH = 20;
    int base = tid * CH;
    int sum = 0;
#pragma unroll
    for (int i = 0; i < CH; i++) {
        int idx = base + i;
        if (idx < NN) sum += g_deg[idx];
    }
    sm[tid] = sum;
    __syncthreads();
    for (int off = 1; off < 1024; off <<= 1) {
        int v = (tid >= off) ? sm[tid - off] : 0;
        __syncthreads();
        sm[tid] += v;
        __syncthreads();
    }
    int run = sm[tid] - sum;
#pragma unroll
    for (int i = 0; i < CH; i++) {
        int idx = base + i;
        if (idx < NN) {
            g_rowptr[idx] = run;
            g_fill[idx] = run;
            run += g_deg[idx];
        }
    }
    if (tid == 0) g_rowptr[NN] = sm[1023];
}

__global__ void scatter_k(const int* __restrict__ ei) {
    int t = blockIdx.x * blockDim.x + threadIdx.x;
    if (t >= QT) return;
#pragma unroll
    for (int r = 0; r < 4; r++) {
        int e = t + r * QT;
        if (e < ET) {
            int src, dst;
            if (e < NE) { src = ei[e]; dst = ei[NE + e]; }
            else        { src = dst = e - NE; }
            int p = atomicAdd(&g_fill[dst], 1);
            g_csr_src[p] = src;
        }
    }
}

// ---------------- as/ad: layer 1 (x fp32, K=128) ----------------
__global__ void asad1_k(const float* __restrict__ x, const float* __restrict__ wsdt) {
    __shared__ int bmax[4];
    if (threadIdx.x < 4) bmax[threadIdx.x] = (int)0x80000000;
    __syncthreads();
    int n = (blockIdx.x * 256 + threadIdx.x) >> 5;   // grid exact: 2500 blocks
    int lane = threadIdx.x & 31;
    float4 xv = *(const float4*)&x[n * 128 + lane * 4];
    float acc[8];
#pragma unroll
    for (int j = 0; j < 8; j++) {
        float4 w = *(const float4*)&wsdt[j * 128 + lane * 4];
        acc[j] = xv.x * w.x + xv.y * w.y + xv.z * w.z + xv.w * w.w;
    }
#pragma unroll
    for (int off = 16; off; off >>= 1)
#pragma unroll
        for (int j = 0; j < 8; j++) acc[j] += __shfl_xor_sync(0xffffffffu, acc[j], off);
    if (lane == 0) {
        *(float4*)&g_as[n * 4] = make_float4(acc[0], acc[1], acc[2], acc[3]);
        *(float4*)&g_ad[n * 4] = make_float4(acc[4], acc[5], acc[6], acc[7]);
#pragma unroll
        for (int j = 0; j < 4; j++) atomicMax(&bmax[j], enc_f(acc[j]));
    }
    __syncthreads();
    if (threadIdx.x < 4) atomicMax(&g_gmax1[threadIdx.x], bmax[threadIdx.x]);
}

// ---------------- as/ad: layer 2 (x2 fp16, K=256) ----------------
__global__ void asad2_k(const float* __restrict__ wsdt) {
    __shared__ int bmax[4];
    if (threadIdx.x < 4) bmax[threadIdx.x] = (int)0x80000000;
    __syncthreads();
    int n = (blockIdx.x * 256 + threadIdx.x) >> 5;
    int lane = threadIdx.x & 31;
    uint4 xv = *(const uint4*)&g_x2h[n * 256 + lane * 8];
    __half2* xh = (__half2*)&xv;
    float xf[8];
#pragma unroll
    for (int t = 0; t < 4; t++) {
        float2 f = __half22float2(xh[t]);
        xf[2 * t] = f.x; xf[2 * t + 1] = f.y;
    }
    float acc[8];
#pragma unroll
    for (int j = 0; j < 8; j++) {
        float4 wA = *(const float4*)&wsdt[j * 256 + lane * 8];
        float4 wB = *(const float4*)&wsdt[j * 256 + lane * 8 + 4];
        acc[j] = xf[0] * wA.x + xf[1] * wA.y + xf[2] * wA.z + xf[3] * wA.w
               + xf[4] * wB.x + xf[5] * wB.y + xf[6] * wB.z + xf[7] * wB.w;
    }
#pragma unroll
    for (int off = 16; off; off >>= 1)
#pragma unroll
        for (int j = 0; j < 8; j++) acc[j] += __shfl_xor_sync(0xffffffffu, acc[j], off);
    if (lane == 0) {
        *(float4*)&g_as[n * 4] = make_float4(acc[0], acc[1], acc[2], acc[3]);
        *(float4*)&g_ad[n * 4] = make_float4(acc[4], acc[5], acc[6], acc[7]);
#pragma unroll
        for (int j = 0; j < 4; j++) atomicMax(&bmax[j], enc_f(acc[j]));
    }
    __syncthreads();
    if (threadIdx.x < 4) atomicMax(&g_gmax2[threadIdx.x], bmax[threadIdx.x]);
}

// ---------------- pipelined fp16 tensor-core GEMM (fp16 output only) ----------------
__device__ __forceinline__ void mma_f16(float* c, const unsigned* a, const unsigned* b) {
    asm volatile(
        "mma.sync.aligned.m16n8k16.row.col.f32.f16.f16.f32 "
        "{%0,%1,%2,%3}, {%4,%5,%6,%7}, {%8,%9}, {%0,%1,%2,%3};\n"
        : "+f"(c[0]), "+f"(c[1]), "+f"(c[2]), "+f"(c[3])
        : "r"(a[0]), "r"(a[1]), "r"(a[2]), "r"(a[3]), "r"(b[0]), "r"(b[1]));
}

template <int KP>
__global__ void mma_gemm_k(const __half* __restrict__ A,
                           const __half* __restrict__ BT,
                           __half* __restrict__ Ch, int M) {
    const int BM = 128, BN = 64, BK = 32, LD = 40;
    __shared__ __align__(16) __half As[2][BM * LD];
    __shared__ __align__(16) __half Bs[2][BN * LD];
    int t = threadIdx.x, lane = t & 31, wid = t >> 5;
    int wm = wid & 3, wn = wid >> 2;
    int bm = blockIdx.y * BM, bn = blockIdx.x * BN;
    float acc[2][4][4] = {};

    int ar = t >> 1, ac = (t & 1) * 16;
    int brow = t >> 2, bcol = (t & 3) * 8;

    auto load_tile = [&](int k0, int st) {
        const __half* ag = A + (size_t)(bm + ar) * KP + k0 + ac;
        unsigned sa = (unsigned)__cvta_generic_to_shared(&As[st][ar * LD + ac]);
        asm volatile("cp.async.ca.shared.global [%0], [%1], 16;\n" :: "r"(sa), "l"(ag) : "memory");
        asm volatile("cp.async.ca.shared.global [%0], [%1], 16;\n" :: "r"(sa + 16), "l"(ag + 8) : "memory");
        const __half* bg = BT + (size_t)(bn + brow) * KP + k0 + bcol;
        unsigned sb = (unsigned)__cvta_generic_to_shared(&Bs[st][brow * LD + bcol]);
        asm volatile("cp.async.ca.shared.global [%0], [%1], 16;\n" :: "r"(sb), "l"(bg) : "memory");
        asm volatile("cp.async.commit_group;\n" ::: "memory");
    };

    load_tile(0, 0);
    const int NT = KP / BK;
    for (int i = 0; i < NT; i++) {
        if (i + 1 < NT) {
            load_tile((i + 1) * BK, (i + 1) & 1);
            asm volatile("cp.async.wait_group 1;\n" ::: "memory");
        } else {
            asm volatile("cp.async.wait_group 0;\n" ::: "memory");
        }
        __syncthreads();
        int st = i & 1;
#pragma unroll
        for (int kk = 0; kk < BK; kk += 16) {
            unsigned af[2][4], bf[2][4];
#pragma unroll
            for (int mt = 0; mt < 2; mt++) {
                unsigned addr = (unsigned)__cvta_generic_to_shared(
                    &As[st][(wm * 32 + mt * 16 + (lane & 15)) * LD + kk + (lane >> 4) * 8]);
                asm volatile("ldmatrix.sync.aligned.m8n8.x4.shared.b16 {%0,%1,%2,%3}, [%4];\n"
                             : "=r"(af[mt][0]), "=r"(af[mt][1]), "=r"(af[mt][2]), "=r"(af[mt][3])
                             : "r"(addr));
            }
#pragma unroll
            for (int nb = 0; nb < 2; nb++) {
                int nr = wn * 32 + nb * 16 + (lane & 7) + ((lane >> 4) << 3);
                int kc = kk + ((lane >> 3) & 1) * 8;
                unsigned addr = (unsigned)__cvta_generic_to_shared(&Bs[st][nr * LD + kc]);
                asm volatile("ldmatrix.sync.aligned.m8n8.x4.shared.b16 {%0,%1,%2,%3}, [%4];\n"
                             : "=r"(bf[nb][0]), "=r"(bf[nb][1]), "=r"(bf[nb][2]), "=r"(bf[nb][3])
                             : "r"(addr));
            }
#pragma unroll
            for (int mt = 0; mt < 2; mt++)
#pragma unroll
                for (int nt = 0; nt < 4; nt++) {
                    unsigned bq[2] = { bf[nt >> 1][(nt & 1) * 2], bf[nt >> 1][(nt & 1) * 2 + 1] };
                    mma_f16(acc[mt][nt], af[mt], bq);
                }
        }
        __syncthreads();
    }

    int g = lane >> 2, tg = lane & 3;
#pragma unroll
    for (int mt = 0; mt < 2; mt++) {
        int r0 = bm + wm * 32 + mt * 16 + g;
#pragma unroll
        for (int nt = 0; nt < 4; nt++) {
            int c = bn + wn * 32 + nt * 8 + tg * 2;
            if (r0 < M)
                *(__half2*)&Ch[(size_t)r0 * 256 + c] = __floats2half2_rn(acc[mt][nt][0], acc[mt][nt][1]);
            if (r0 + 8 < M)
                *(__half2*)&Ch[(size_t)(r0 + 8) * 256 + c] = __floats2half2_rn(acc[mt][nt][2], acc[mt][nt][3]);
        }
    }
}

// ---------------- GAT aggregation: one warp per node, all 4 heads ----------------
__global__ void agg_k(const __half* __restrict__ hh, const float* __restrict__ bias,
                      int layer1, const int* __restrict__ gmax) {
    __shared__ float ps[8][32][4];
    int n = (blockIdx.x * 256 + threadIdx.x) >> 5;   // grid exact: 2500 blocks
    int lane = threadIdx.x & 31;
    int w = threadIdx.x >> 5;
    int beg = g_rowptr[n], end = g_rowptr[n + 1];
    float4 ad4 = *(const float4*)&g_ad[n * 4];
    // per-head upper bound on logits: leaky(gmax_as + ad)
    float m0 = dec_f(gmax[0]) + ad4.x; m0 = fmaxf(m0, 0.2f * m0);
    float m1 = dec_f(gmax[1]) + ad4.y; m1 = fmaxf(m1, 0.2f * m1);
    float m2 = dec_f(gmax[2]) + ad4.z; m2 = fmaxf(m2, 0.2f * m2);
    float m3 = dec_f(gmax[3]) + ad4.w; m3 = fmaxf(m3, 0.2f * m3);

    float a[8] = {};
    float s0 = 0.f, s1 = 0.f, s2 = 0.f, s3 = 0.f;
    int hd = lane >> 3;
    const __half* hp = hh + lane * 8;

    for (int base = beg; base < end; base += 32) {
        int i = base + lane;
        float p0 = 0.f, p1 = 0.f, p2 = 0.f, p3 = 0.f;
        int sj = 0;
        if (i < end) {
            sj = g_csr_src[i];
            float4 as4 = *(const float4*)&g_as[sj * 4];
            float e;
            e = as4.x + ad4.x; e = fmaxf(e, 0.2f * e); p0 = __expf(e - m0);
            e = as4.y + ad4.y; e = fmaxf(e, 0.2f * e); p1 = __expf(e - m1);
            e = as4.z + ad4.z; e = fmaxf(e, 0.2f * e); p2 = __expf(e - m2);
            e = as4.w + ad4.w; e = fmaxf(e, 0.2f * e); p3 = __expf(e - m3);
        }
        s0 += p0; s1 += p1; s2 += p2; s3 += p3;
        ps[w][lane][0] = p0; ps[w][lane][1] = p1;
        ps[w][lane][2] = p2; ps[w][lane][3] = p3;
        __syncwarp();
        int cnt = min(32, end - base);
#pragma unroll 8
        for (int j = 0; j < cnt; j++) {
            int sc = __shfl_sync(0xffffffffu, sj, j);
            float p = ps[w][j][hd];
            uint4 v = *(const uint4*)(hp + sc * HC);
            __half2* hv = (__half2*)&v;
            float2 f0 = __half22float2(hv[0]);
            float2 f1 = __half22float2(hv[1]);
            float2 f2 = __half22float2(hv[2]);
            float2 f3 = __half22float2(hv[3]);
            a[0] += p * f0.x; a[1] += p * f0.y;
            a[2] += p * f1.x; a[3] += p * f1.y;
            a[4] += p * f2.x; a[5] += p * f2.y;
            a[6] += p * f3.x; a[7] += p * f3.y;
        }
        __syncwarp();
    }
#pragma unroll
    for (int off = 16; off; off >>= 1) {
        s0 += __shfl_xor_sync(0xffffffffu, s0, off);
        s1 += __shfl_xor_sync(0xffffffffu, s1, off);
        s2 += __shfl_xor_sync(0xffffffffu, s2, off);
        s3 += __shfl_xor_sync(0xffffffffu, s3, off);
    }
    float sv = (hd == 0) ? s0 : (hd == 1) ? s1 : (hd == 2) ? s2 : s3;
    float inv = 1.f / sv;
    int ch = lane * 8;
    if (layer1) {
        float4 bA = *(const float4*)&bias[ch];
        float4 bB = *(const float4*)&bias[ch + 4];
        float v[8];
        v[0] = a[0] * inv + bA.x; v[1] = a[1] * inv + bA.y;
        v[2] = a[2] * inv + bA.z; v[3] = a[3] * inv + bA.w;
        v[4] = a[4] * inv + bB.x; v[5] = a[5] * inv + bB.y;
        v[6] = a[6] * inv + bB.z; v[7] = a[7] * inv + bB.w;
#pragma unroll
        for (int t = 0; t < 8; t++) v[t] = (v[t] > 0.f) ? v[t] : (__expf(v[t]) - 1.f);
        uint4 o;
        __half2* oh = (__half2*)&o;
        oh[0] = __floats2half2_rn(v[0], v[1]);
        oh[1] = __floats2half2_rn(v[2], v[3]);
        oh[2] = __floats2half2_rn(v[4], v[5]);
        oh[3] = __floats2half2_rn(v[6], v[7]);
        *(uint4*)&g_x2h[n * 256 + ch] = o;
    } else {
        *(float4*)&g_agg2[n * HC + ch] =
            make_float4(a[0] * inv, a[1] * inv, a[2] * inv, a[3] * inv);
        *(float4*)&g_agg2[n * HC + ch + 4] =
            make_float4(a[4] * inv, a[5] * inv, a[6] * inv, a[7] * inv);
    }
}

// ---------------- tail: head-mean + b2, then @Wout + bout ----------------
__global__ void final_k(const float* __restrict__ b2, const float* __restrict__ Wout,
                        const float* __restrict__ bout, float* __restrict__ out) {
    __shared__ float Ws[CC * 16];
    int t = threadIdx.x;
    for (int i = t; i < CC * 16; i += blockDim.x) Ws[i] = Wout[i];
    __syncthreads();
    int warp = (blockIdx.x * blockDim.x + t) >> 5;
    int lane = t & 31;
    if (warp >= NN) return;
    int n = warp;
    int c0 = 2 * lane;
    float v0 = 0.f, v1 = 0.f;
#pragma unroll
    for (int hd = 0; hd < FH; hd++) {
        float2 hv = *(const float2*)&g_agg2[n * HC + hd * CC + c0];
        v0 += hv.x; v1 += hv.y;
    }
    v0 = v0 * 0.25f + b2[c0];
    v1 = v1 * 0.25f + b2[c0 + 1];
    float p[16];
#pragma unroll
    for (int k = 0; k < 16; k++)
        p[k] = v0 * Ws[c0 * 16 + k] + v1 * Ws[(c0 + 1) * 16 + k];
#pragma unroll
    for (int k = 0; k < 16; k++) {
#pragma unroll
        for (int off = 16; off; off >>= 1)
            p[k] += __shfl_xor_sync(0xffffffffu, p[k], off);
    }
    if (lane < 16) out[n * 16 + lane] = p[lane] + bout[lane];
}

// ---------------- launch ----------------
extern "C" void kernel_launch(void* const* d_in, const int* in_sizes, int n_in,
                              void* d_out, int out_size) {
    const float* x     = (const float*)d_in[0];
    const int*   ei    = (const int*)d_in[1];
    const float* W1    = (const float*)d_in[2];
    const float* atts1 = (const float*)d_in[3];
    const float* attd1 = (const float*)d_in[4];
    const float* b1    = (const float*)d_in[5];
    const float* W2    = (const float*)d_in[6];
    const float* atts2 = (const float*)d_in[7];
    const float* attd2 = (const float*)d_in[8];
    const float* b2    = (const float*)d_in[9];
    const float* Wout  = (const float*)d_in[10];
    const float* bout  = (const float*)d_in[11];
    float* out = (float*)d_out;

    __half* ghh;   cudaGetSymbolAddress((void**)&ghh, g_hh);
    __half* gxh;   cudaGetSymbolAddress((void**)&gxh, g_xh);
    __half* gx2h;  cudaGetSymbolAddress((void**)&gx2h, g_x2h);
    __half* gbt1;  cudaGetSymbolAddress((void**)&gbt1, g_bt1);
    __half* gbt2;  cudaGetSymbolAddress((void**)&gbt2, g_bt2);
    float* gwsd1;  cudaGetSymbolAddress((void**)&gwsd1, g_wsd1);
    float* gwsd2;  cudaGetSymbolAddress((void**)&gwsd2, g_wsd2);
    int* ggm1;     cudaGetSymbolAddress((void**)&ggm1, g_gmax1);
    int* ggm2;     cudaGetSymbolAddress((void**)&ggm2, g_gmax2);

    // prep (wsd1 also resets the gmax slots)
    wsd_k<<<4, 256>>>(W1, atts1, attd1, gwsd1, 128, 1);
    wsd_k<<<8, 256>>>(W2, atts2, attd2, gwsd2, 256, 0);
    cvt_x_k<<<(NN * 128 + 255) / 256, 256>>>(x);
    asad1_k<<<NN / 8, 256>>>(x, gwsd1);           // 4th launch -> profiled

    // CSR build
    zero_deg_k<<<(NN + 255) / 256, 256>>>();
    hist_k<<<(QT + 255) / 256, 256>>>(ei);
    scan_k<<<1, 1024>>>();
    scatter_k<<<(QT + 255) / 256, 256>>>(ei);

    // weights to fp16
    wt_k<128><<<(128 * 256 + 255) / 256, 256>>>(W1, gbt1);
    wt_k<256><<<(256 * 256 + 255) / 256, 256>>>(W2, gbt2);

    // ---- layer 1 ----
    mma_gemm_k<128><<<dim3(4, NNP / 128), 256>>>(gxh, gbt1, ghh, NN);
    agg_k<<<NN / 8, 256>>>(ghh, b1, 1, ggm1);     // writes g_x2h

    // ---- layer 2 ----
    mma_gemm_k<256><<<dim3(4, NNP / 128), 256>>>(gx2h, gbt2, ghh, NN);
    asad2_k<<<NN / 8, 256>>>(gwsd2);
    agg_k<<<NN / 8, 256>>>(ghh, nullptr, 0, ggm2);

    // ---- tail ----
    final_k<<<(NN * 32 + 255) / 256, 256>>>(b2, Wout, bout, out);
}